// round 1
// baseline (speedup 1.0000x reference)
#include <cuda_runtime.h>
#include <stdint.h>

// ---------------- problem constants ----------------
constexpr int BATCH = 4, SEQ = 1024, CH = 768, HEADS = 12, HDIM = 64;
constexpr int ROWS = BATCH * SEQ;   // 4096
constexpr int C3v  = 3 * CH;        // 2304
constexpr int NBH  = BATCH * HEADS; // 48

// ---------------- scratch (__device__ globals; no runtime alloc) ----------------
__device__ __align__(256) int8_t g_x0q [ROWS * CH];
__device__ __align__(256) int8_t g_wqkv[C3v * CH];
__device__            int    g_biasi[C3v];
__device__ __align__(256) int8_t g_wproj[CH * CH];
__device__ __align__(256) int    g_qkv [ROWS * C3v];            // 37.7 MB
__device__ __align__(256) int8_t g_q2  [NBH * SEQ * HDIM];
__device__ __align__(256) int8_t g_k2  [NBH * SEQ * HDIM];
__device__ __align__(256) int8_t g_v2t [NBH * HDIM * SEQ];      // transposed V
__device__ __align__(256) float  g_expo[NBH * SEQ * SEQ];       // 201 MB
__device__ __align__(256) int8_t g_attn2[NBH * SEQ * SEQ];      // 50 MB
__device__ __align__(256) int8_t g_x1q [ROWS * CH];
__device__            float  g_sc[8]; // 0:a_in 1:aq 2:ak 3:av 4:am 5:ap 6:ce 7:am*av

__device__ __forceinline__ float clip8(float x) { return fminf(fmaxf(x, -8.f), 7.f); }
__device__ __forceinline__ int8_t q8(float x) { return (int8_t)(int)rintf(clip8(x)); }

// ---------------- scalar means ----------------
__global__ void k_scalars(const float* __restrict__ qkv_act_alpha,
                          const float* __restrict__ proj_act_alpha,
                          const float* __restrict__ q_alpha,
                          const float* __restrict__ k_alpha,
                          const float* __restrict__ v_alpha,
                          const float* __restrict__ attn_alpha) {
    __shared__ float sh[256];
    int t = threadIdx.x;
    float s = 0.f;
    for (int i = t; i < CH; i += 256) s += qkv_act_alpha[i];
    sh[t] = s; __syncthreads();
    for (int o = 128; o > 0; o >>= 1) { if (t < o) sh[t] += sh[t + o]; __syncthreads(); }
    float a_in = sh[0] / (float)CH;
    __syncthreads();
    s = 0.f;
    for (int i = t; i < CH; i += 256) s += proj_act_alpha[i];
    sh[t] = s; __syncthreads();
    for (int o = 128; o > 0; o >>= 1) { if (t < o) sh[t] += sh[t + o]; __syncthreads(); }
    float ap = sh[0] / (float)CH;
    if (t == 0) {
        float aq = 0.f, ak = 0.f, av = 0.f, am = 0.f;
        for (int i = 0; i < HEADS; i++) { aq += q_alpha[i]; ak += k_alpha[i]; av += v_alpha[i]; am += attn_alpha[i]; }
        aq /= HEADS; ak /= HEADS; av /= HEADS; am /= HEADS;
        g_sc[0] = a_in; g_sc[1] = aq; g_sc[2] = ak; g_sc[3] = av; g_sc[4] = am; g_sc[5] = ap;
        g_sc[6] = 1.4426950408889634f * ((0.125f * aq) * ak);  // LOG2E * head_scale*aq*ak
        g_sc[7] = am * av;
    }
}

// ---------------- quantizers ----------------
__global__ void k_quant_x0(const float* __restrict__ x0) {
    int i = blockIdx.x * blockDim.x + threadIdx.x;
    if (i < ROWS * CH) g_x0q[i] = q8(x0[i] / g_sc[0]);
}
__global__ void k_quant_wqkv(const float* __restrict__ w, const float* __restrict__ alpha,
                             const float* __restrict__ bvec) {
    int i = blockIdx.x * blockDim.x + threadIdx.x;
    if (i < C3v * CH) {
        int o = i / CH;
        g_wqkv[i] = q8(w[i] / alpha[o]);
        if ((i % CH) == 0) g_biasi[o] = (int)truncf(bvec[o] / g_sc[0] / alpha[o]);
    }
}
__global__ void k_quant_wproj(const float* __restrict__ w, const float* __restrict__ alpha) {
    int i = blockIdx.x * blockDim.x + threadIdx.x;
    if (i < CH * CH) {
        int o = i / CH;
        g_wproj[i] = q8(w[i] / alpha[o]);
    }
}

// ---------------- integer mean/var norm + q/k/v quantization ----------------
// grid: (SEQ/64, 1, NBH), block 64 threads; thread t owns row n0+t of head (b,h).
__global__ void k_norm(const float* __restrict__ qkv_alpha,
                       const float* __restrict__ nqw, const float* __restrict__ nqb,
                       const float* __restrict__ nkw, const float* __restrict__ nkb) {
    int bh = blockIdx.z, b = bh / HEADS, h = bh % HEADS;
    int n0 = blockIdx.x * 64;
    int t = threadIdx.x;
    __shared__ int sm[64][65];
    __shared__ float alq[64], alk[64], alv[64], wq_s[64], bq_s[64], wk_s[64], bk_s[64];
    alq[t] = qkv_alpha[h * HDIM + t];
    alk[t] = qkv_alpha[CH + h * HDIM + t];
    alv[t] = g_sc[0] * qkv_alpha[2 * CH + h * HDIM + t];
    wq_s[t] = nqw[t]; bq_s[t] = nqb[t]; wk_s[t] = nkw[t]; bk_s[t] = nkb[t];
    float aq = g_sc[1], ak = g_sc[2], av = g_sc[3];
    __syncthreads();

    // ---- Q branch ----
    for (int r = 0; r < 64; r++)
        sm[r][t] = g_qkv[(long)(b * SEQ + n0 + r) * C3v + h * HDIM + t];
    __syncthreads();
    {
        int m = 0, vv = 0;
        for (int d = 0; d < HDIM; d++) {
            float xf = (float)sm[t][d] * alq[d];
            int xi = (int)xf;                     // trunc toward zero (matches astype int32)
            int dd = xi - m;
            int c = 1024 / (d + 1);
            m += (dd * c) >> 10;                  // floor div by 1024
            vv += dd * (xi - m);
        }
        float mu = (float)m;
        float den = sqrtf((float)vv / 64.f) + 1e-5f;
        int8_t* outq = g_q2 + ((long)bh * SEQ + n0 + t) * HDIM;
        for (int d = 0; d < HDIM; d++) {
            float xf = (float)sm[t][d] * alq[d];
            float q1 = (xf - mu) / den;
            outq[d] = q8((q1 + bq_s[d] / wq_s[d]) * wq_s[d] / aq);
        }
    }
    __syncthreads();

    // ---- K branch ----
    for (int r = 0; r < 64; r++)
        sm[r][t] = g_qkv[(long)(b * SEQ + n0 + r) * C3v + CH + h * HDIM + t];
    __syncthreads();
    {
        int m = 0, vv = 0;
        for (int d = 0; d < HDIM; d++) {
            float xf = (float)sm[t][d] * alk[d];
            int xi = (int)xf;
            int dd = xi - m;
            int c = 1024 / (d + 1);
            m += (dd * c) >> 10;
            vv += dd * (xi - m);
        }
        float mu = (float)m;
        float den = sqrtf((float)vv / 64.f) + 1e-5f;
        int8_t* outk = g_k2 + ((long)bh * SEQ + n0 + t) * HDIM;
        for (int d = 0; d < HDIM; d++) {
            float xf = (float)sm[t][d] * alk[d];
            float k1 = (xf - mu) / den;
            outk[d] = q8((k1 + bk_s[d] / wk_s[d]) * wk_s[d] / ak);
        }
    }
    __syncthreads();

    // ---- V branch (write transposed: g_v2t[bh][d][n]) ----
    for (int r = 0; r < 64; r++)
        sm[r][t] = g_qkv[(long)(b * SEQ + n0 + r) * C3v + 2 * CH + h * HDIM + t];
    __syncthreads();
    {
        int8_t* outv = g_v2t + (long)bh * HDIM * SEQ;
        for (int d = 0; d < HDIM; d++)
            outv[d * SEQ + n0 + t] = q8((float)sm[t][d] * alv[d] / av);
    }
}

// ---------------- row-sum + attention quantization ----------------
__global__ void k_attnq() {
    int warp = threadIdx.x >> 5, lane = threadIdx.x & 31;
    long row = (long)blockIdx.x * 8 + warp;   // row in [0, NBH*SEQ)
    const float* p = g_expo + row * SEQ;
    float s = 0.f;
    for (int j = lane; j < SEQ; j += 32) s += p[j];
    #pragma unroll
    for (int o = 16; o > 0; o >>= 1) s += __shfl_xor_sync(0xffffffffu, s, o);
    float am = g_sc[4];
    int8_t* o8 = g_attn2 + row * SEQ;
    for (int j = lane; j < SEQ; j += 32)
        o8[j] = q8(p[j] / s / am);
}

// ---------------- generic batched int8 MMA GEMM (m16n8k32 s8) ----------------
// A: [M][K] row-major int8; B: [N][K] row-major int8 (serves as col-major operand).
// MODE 0: qkv  (out=g_qkv int32 + bias)
// MODE 1: q@kT (out=g_expo, exp2-softmax numerator epilogue), batched over z=NBH
// MODE 2: attn@v (out=g_x1q int8, re-quant epilogue), batched over z=NBH
// MODE 3: proj (out=d_out fp32, scale+bias epilogue)
template <int MODE>
__global__ void gemm_s8(float* __restrict__ outf,
                        const float* __restrict__ e1, const float* __restrict__ e2) {
    constexpr int M  = (MODE == 0) ? 4096 : (MODE == 3) ? 4096 : 1024;
    constexpr int N  = (MODE == 0) ? 2304 : (MODE == 1) ? 1024 : (MODE == 2) ? 64 : 768;
    constexpr int K  = (MODE == 0) ? 768  : (MODE == 1) ? 64   : (MODE == 2) ? 1024 : 768;
    constexpr int BM = 128;
    constexpr int BN = (MODE == 2) ? 64 : 128;
    constexpr int BK = 64;
    constexpr int WR = 2;
    constexpr int WC = (MODE == 2) ? 2 : 4;
    constexpr int NWARP = WR * WC;
    constexpr int NTHR  = NWARP * 32;
    constexpr int WM = BM / WR, WN = BN / WC;
    constexpr int MI = WM / 16, NI = WN / 8;
    constexpr int SAS = BK + 16;   // padded byte stride (bank-conflict-free frag reads)

    __shared__ __align__(16) int8_t As[BM * SAS];
    __shared__ __align__(16) int8_t Bs[BN * SAS];

    int bz = blockIdx.z;
    const int8_t* A;
    const int8_t* Bw;
    if constexpr (MODE == 0)      { A = g_x0q;                        Bw = g_wqkv; }
    else if constexpr (MODE == 1) { A = g_q2 + (long)bz * SEQ * HDIM;  Bw = g_k2 + (long)bz * SEQ * HDIM; }
    else if constexpr (MODE == 2) { A = g_attn2 + (long)bz * SEQ * SEQ; Bw = g_v2t + (long)bz * HDIM * SEQ; }
    else                          { A = g_x1q;                        Bw = g_wproj; }

    int tid = threadIdx.x;
    int warp = tid >> 5, lane = tid & 31;
    int wr = warp / WC, wc = warp % WC;
    int g = lane >> 2, q4 = lane & 3;
    int rowBase = blockIdx.y * BM;
    int colBase = blockIdx.x * BN;

    int acc[MI][NI][4];
    #pragma unroll
    for (int i = 0; i < MI; i++)
        #pragma unroll
        for (int j = 0; j < NI; j++)
            #pragma unroll
            for (int v = 0; v < 4; v++) acc[i][j][v] = 0;

    for (int k0 = 0; k0 < K; k0 += BK) {
        // stage A tile
        constexpr int AV = BM * BK / 16;
        #pragma unroll
        for (int idx = tid; idx < AV; idx += NTHR) {
            int r = idx / (BK / 16), seg = idx % (BK / 16);
            *(int4*)&As[r * SAS + seg * 16] =
                *(const int4*)&A[(long)(rowBase + r) * K + k0 + seg * 16];
        }
        // stage B tile
        constexpr int BV = BN * BK / 16;
        #pragma unroll
        for (int idx = tid; idx < BV; idx += NTHR) {
            int r = idx / (BK / 16), seg = idx % (BK / 16);
            *(int4*)&Bs[r * SAS + seg * 16] =
                *(const int4*)&Bw[(long)(colBase + r) * K + k0 + seg * 16];
        }
        __syncthreads();

        #pragma unroll
        for (int ks = 0; ks < BK; ks += 32) {
            uint32_t bf[NI][2];
            #pragma unroll
            for (int j = 0; j < NI; j++) {
                const int8_t* bp = &Bs[(wc * WN + j * 8 + g) * SAS + ks + q4 * 4];
                bf[j][0] = *(const uint32_t*)bp;
                bf[j][1] = *(const uint32_t*)(bp + 16);
            }
            #pragma unroll
            for (int i = 0; i < MI; i++) {
                const int8_t* ap0 = &As[(wr * WM + i * 16 + g) * SAS + ks + q4 * 4];
                uint32_t a0 = *(const uint32_t*)ap0;
                uint32_t a2 = *(const uint32_t*)(ap0 + 16);
                const int8_t* ap1 = ap0 + 8 * SAS;
                uint32_t a1 = *(const uint32_t*)ap1;
                uint32_t a3 = *(const uint32_t*)(ap1 + 16);
                #pragma unroll
                for (int j = 0; j < NI; j++) {
                    asm volatile(
                        "mma.sync.aligned.m16n8k32.row.col.s32.s8.s8.s32 "
                        "{%0,%1,%2,%3},{%4,%5,%6,%7},{%8,%9},{%0,%1,%2,%3};"
                        : "+r"(acc[i][j][0]), "+r"(acc[i][j][1]),
                          "+r"(acc[i][j][2]), "+r"(acc[i][j][3])
                        : "r"(a0), "r"(a1), "r"(a2), "r"(a3),
                          "r"(bf[j][0]), "r"(bf[j][1]));
                }
            }
        }
        __syncthreads();
    }

    // epilogue
    float s5 = g_sc[5], s6 = g_sc[6], s7 = g_sc[7];
    int rb = rowBase + wr * WM;
    int cb = colBase + wc * WN;
    #pragma unroll
    for (int i = 0; i < MI; i++) {
        #pragma unroll
        for (int j = 0; j < NI; j++) {
            #pragma unroll
            for (int v = 0; v < 4; v++) {
                int rr = rb + i * 16 + g + (v >> 1) * 8;
                int cc = cb + j * 8 + q4 * 2 + (v & 1);
                int a = acc[i][j][v];
                if constexpr (MODE == 0) {
                    g_qkv[(long)rr * C3v + cc] = a + g_biasi[cc];
                } else if constexpr (MODE == 1) {
                    float e = s6 * (float)a;
                    float f = floorf(e);
                    float p = exp2f(f) * (1.0f + (e - f));
                    g_expo[(long)bz * SEQ * SEQ + (long)rr * SEQ + cc] = p;
                } else if constexpr (MODE == 2) {
                    int b_ = bz / HEADS, h_ = bz % HEADS;
                    float x = (float)a * s7 / s5;
                    g_x1q[((long)(b_ * SEQ + rr)) * CH + h_ * HDIM + cc] = q8(x);
                } else {
                    outf[(long)rr * CH + cc] = ((float)a * e1[cc]) * s5 + e2[cc];
                }
            }
        }
    }
}

// ---------------- launcher ----------------
extern "C" void kernel_launch(void* const* d_in, const int* in_sizes, int n_in,
                              void* d_out, int out_size) {
    const float* x0             = (const float*)d_in[0];
    const float* qkv_w          = (const float*)d_in[1];
    const float* qkv_b          = (const float*)d_in[2];
    const float* qkv_alpha      = (const float*)d_in[3];
    const float* qkv_act_alpha  = (const float*)d_in[4];
    const float* proj_w         = (const float*)d_in[5];
    const float* proj_b         = (const float*)d_in[6];
    const float* proj_alpha     = (const float*)d_in[7];
    const float* proj_act_alpha = (const float*)d_in[8];
    const float* norm_q_w       = (const float*)d_in[9];
    const float* norm_q_b       = (const float*)d_in[10];
    const float* norm_k_w       = (const float*)d_in[11];
    const float* norm_k_b       = (const float*)d_in[12];
    const float* q_alpha        = (const float*)d_in[13];
    const float* k_alpha        = (const float*)d_in[14];
    const float* v_alpha        = (const float*)d_in[15];
    const float* attn_alpha     = (const float*)d_in[16];
    float* out = (float*)d_out;

    k_scalars<<<1, 256>>>(qkv_act_alpha, proj_act_alpha, q_alpha, k_alpha, v_alpha, attn_alpha);
    k_quant_x0<<<(ROWS * CH + 255) / 256, 256>>>(x0);
    k_quant_wqkv<<<(C3v * CH + 255) / 256, 256>>>(qkv_w, qkv_alpha, qkv_b);
    k_quant_wproj<<<(CH * CH + 255) / 256, 256>>>(proj_w, proj_alpha);

    // QKV GEMM: 4096 x 2304 x 768
    gemm_s8<0><<<dim3(C3v / 128, ROWS / 128, 1), 256>>>(nullptr, nullptr, nullptr);

    // per-row integer mean/var + quantization
    k_norm<<<dim3(SEQ / 64, 1, NBH), 64>>>(qkv_alpha, norm_q_w, norm_q_b, norm_k_w, norm_k_b);

    // Q @ K^T with exp2-softmax-numerator epilogue (batched over heads)
    gemm_s8<1><<<dim3(SEQ / 128, SEQ / 128, NBH), 256>>>(nullptr, nullptr, nullptr);

    // row sums + attention quantization
    k_attnq<<<(NBH * SEQ) / 8, 256>>>();

    // attn @ V, requantize to x1 int8 (batched over heads)
    gemm_s8<2><<<dim3(1, SEQ / 128, NBH), 128>>>(nullptr, nullptr, nullptr);

    // projection GEMM: 4096 x 768 x 768, fp32 epilogue to d_out
    gemm_s8<3><<<dim3(CH / 128, ROWS / 128, 1), 256>>>(out, proj_alpha, proj_b);
}

// round 2
// speedup vs baseline: 1.0319x; 1.0319x over previous
#include <cuda_runtime.h>
#include <stdint.h>

// ---------------- problem constants ----------------
constexpr int BATCH = 4, SEQ = 1024, CH = 768, HEADS = 12, HDIM = 64;
constexpr int ROWS = BATCH * SEQ;   // 4096
constexpr int C3v  = 3 * CH;        // 2304
constexpr int NBH  = BATCH * HEADS; // 48

// ---------------- scratch (__device__ globals; no runtime alloc) ----------------
__device__ __align__(256) int8_t g_x0q [ROWS * CH];
__device__ __align__(256) int8_t g_wqkv[C3v * CH];
__device__            int    g_biasi[C3v];
__device__ __align__(256) int8_t g_wproj[CH * CH];
__device__ __align__(256) int    g_qkv [ROWS * C3v];            // 37.7 MB
__device__ __align__(256) int8_t g_q2  [NBH * SEQ * HDIM];
__device__ __align__(256) int8_t g_k2  [NBH * SEQ * HDIM];
__device__ __align__(256) int8_t g_v2t [NBH * HDIM * SEQ];      // transposed V
__device__ __align__(256) int8_t g_x1q [ROWS * CH];
__device__            float  g_sc[8]; // 0:a_in 1:aq 2:ak 3:av 4:am 5:ap 6:ce 7:am*av

__device__ __forceinline__ float clip8(float x) { return fminf(fmaxf(x, -8.f), 7.f); }
__device__ __forceinline__ int8_t q8(float x) { return (int8_t)(int)rintf(clip8(x)); }

// ---------------- scalar means ----------------
__global__ void k_scalars(const float* __restrict__ qkv_act_alpha,
                          const float* __restrict__ proj_act_alpha,
                          const float* __restrict__ q_alpha,
                          const float* __restrict__ k_alpha,
                          const float* __restrict__ v_alpha,
                          const float* __restrict__ attn_alpha) {
    __shared__ float sh[256];
    int t = threadIdx.x;
    float s = 0.f;
    for (int i = t; i < CH; i += 256) s += qkv_act_alpha[i];
    sh[t] = s; __syncthreads();
    for (int o = 128; o > 0; o >>= 1) { if (t < o) sh[t] += sh[t + o]; __syncthreads(); }
    float a_in = sh[0] / (float)CH;
    __syncthreads();
    s = 0.f;
    for (int i = t; i < CH; i += 256) s += proj_act_alpha[i];
    sh[t] = s; __syncthreads();
    for (int o = 128; o > 0; o >>= 1) { if (t < o) sh[t] += sh[t + o]; __syncthreads(); }
    float ap = sh[0] / (float)CH;
    if (t == 0) {
        float aq = 0.f, ak = 0.f, av = 0.f, am = 0.f;
        for (int i = 0; i < HEADS; i++) { aq += q_alpha[i]; ak += k_alpha[i]; av += v_alpha[i]; am += attn_alpha[i]; }
        aq /= HEADS; ak /= HEADS; av /= HEADS; am /= HEADS;
        g_sc[0] = a_in; g_sc[1] = aq; g_sc[2] = ak; g_sc[3] = av; g_sc[4] = am; g_sc[5] = ap;
        g_sc[6] = 1.4426950408889634f * ((0.125f * aq) * ak);  // LOG2E * head_scale*aq*ak
        g_sc[7] = am * av;
    }
}

// ---------------- quantizers ----------------
__global__ void k_quant_x0(const float* __restrict__ x0) {
    int i = blockIdx.x * blockDim.x + threadIdx.x;
    if (i < ROWS * CH) g_x0q[i] = q8(x0[i] / g_sc[0]);
}
__global__ void k_quant_wqkv(const float* __restrict__ w, const float* __restrict__ alpha,
                             const float* __restrict__ bvec) {
    int i = blockIdx.x * blockDim.x + threadIdx.x;
    if (i < C3v * CH) {
        int o = i / CH;
        g_wqkv[i] = q8(w[i] / alpha[o]);
        if ((i % CH) == 0) g_biasi[o] = (int)truncf(bvec[o] / g_sc[0] / alpha[o]);
    }
}
__global__ void k_quant_wproj(const float* __restrict__ w, const float* __restrict__ alpha) {
    int i = blockIdx.x * blockDim.x + threadIdx.x;
    if (i < CH * CH) {
        int o = i / CH;
        g_wproj[i] = q8(w[i] / alpha[o]);
    }
}

// ---------------- integer mean/var norm + q/k/v quantization ----------------
__global__ void k_norm(const float* __restrict__ qkv_alpha,
                       const float* __restrict__ nqw, const float* __restrict__ nqb,
                       const float* __restrict__ nkw, const float* __restrict__ nkb) {
    int bh = blockIdx.z, b = bh / HEADS, h = bh % HEADS;
    int n0 = blockIdx.x * 64;
    int t = threadIdx.x;
    __shared__ int sm[64][65];
    __shared__ float alq[64], alk[64], alv[64], wq_s[64], bq_s[64], wk_s[64], bk_s[64];
    alq[t] = qkv_alpha[h * HDIM + t];
    alk[t] = qkv_alpha[CH + h * HDIM + t];
    alv[t] = g_sc[0] * qkv_alpha[2 * CH + h * HDIM + t];
    wq_s[t] = nqw[t]; bq_s[t] = nqb[t]; wk_s[t] = nkw[t]; bk_s[t] = nkb[t];
    float aq = g_sc[1], ak = g_sc[2], av = g_sc[3];
    __syncthreads();

    // ---- Q branch ----
    for (int r = 0; r < 64; r++)
        sm[r][t] = g_qkv[(long)(b * SEQ + n0 + r) * C3v + h * HDIM + t];
    __syncthreads();
    {
        int m = 0, vv = 0;
        for (int d = 0; d < HDIM; d++) {
            float xf = (float)sm[t][d] * alq[d];
            int xi = (int)xf;
            int dd = xi - m;
            int c = 1024 / (d + 1);
            m += (dd * c) >> 10;
            vv += dd * (xi - m);
        }
        float mu = (float)m;
        float den = sqrtf((float)vv / 64.f) + 1e-5f;
        int8_t* outq = g_q2 + ((long)bh * SEQ + n0 + t) * HDIM;
        for (int d = 0; d < HDIM; d++) {
            float xf = (float)sm[t][d] * alq[d];
            float q1 = (xf - mu) / den;
            outq[d] = q8((q1 + bq_s[d] / wq_s[d]) * wq_s[d] / aq);
        }
    }
    __syncthreads();

    // ---- K branch ----
    for (int r = 0; r < 64; r++)
        sm[r][t] = g_qkv[(long)(b * SEQ + n0 + r) * C3v + CH + h * HDIM + t];
    __syncthreads();
    {
        int m = 0, vv = 0;
        for (int d = 0; d < HDIM; d++) {
            float xf = (float)sm[t][d] * alk[d];
            int xi = (int)xf;
            int dd = xi - m;
            int c = 1024 / (d + 1);
            m += (dd * c) >> 10;
            vv += dd * (xi - m);
        }
        float mu = (float)m;
        float den = sqrtf((float)vv / 64.f) + 1e-5f;
        int8_t* outk = g_k2 + ((long)bh * SEQ + n0 + t) * HDIM;
        for (int d = 0; d < HDIM; d++) {
            float xf = (float)sm[t][d] * alk[d];
            float k1 = (xf - mu) / den;
            outk[d] = q8((k1 + bk_s[d] / wk_s[d]) * wk_s[d] / ak);
        }
    }
    __syncthreads();

    // ---- V branch (write transposed: g_v2t[bh][d][n]) ----
    for (int r = 0; r < 64; r++)
        sm[r][t] = g_qkv[(long)(b * SEQ + n0 + r) * C3v + 2 * CH + h * HDIM + t];
    __syncthreads();
    {
        int8_t* outv = g_v2t + (long)bh * HDIM * SEQ;
        for (int d = 0; d < HDIM; d++)
            outv[d * SEQ + n0 + t] = q8((float)sm[t][d] * alv[d] / av);
    }
}

// ---------------- fused flash-style attention ----------------
// grid (SEQ/128, NBH), block 256 (8 warps, 2x4).
// smem: K (1024x64, stride 80), Vt (64x1024, stride 1040), Q (128x64, stride 80),
//       attn chunk (128x128, stride 144), rowsum[128].
constexpr int OFF_K = 0;
constexpr int OFF_V = 81920;
constexpr int OFF_Q = 148480;
constexpr int OFF_A = 158720;
constexpr int OFF_S = 177152;
constexpr int SMEM_FUSED = 177664;

__global__ void __launch_bounds__(256, 1) k_attn_fused() {
    extern __shared__ __align__(16) int8_t sh[];
    int8_t* Ksm = sh + OFF_K;
    int8_t* Vsm = sh + OFF_V;
    int8_t* Qsm = sh + OFF_Q;
    int8_t* Asm = sh + OFF_A;
    float*  rs  = (float*)(sh + OFF_S);

    int bh = blockIdx.y, b = bh / HEADS, h = bh % HEADS;
    int qBase = blockIdx.x * 128;
    int tid = threadIdx.x, warp = tid >> 5, lane = tid & 31;
    int g = lane >> 2, q4 = lane & 3;
    int wr = warp >> 2, wc = warp & 3;

    const int8_t* Qg = g_q2 + ((long)bh * SEQ + qBase) * HDIM;
    const int8_t* Kg = g_k2 + (long)bh * SEQ * HDIM;
    const int8_t* Vg = g_v2t + (long)bh * HDIM * SEQ;

    for (int idx = tid; idx < 512; idx += 256) {
        int r = idx >> 2, s = idx & 3;
        *(int4*)&Qsm[r * 80 + s * 16] = *(const int4*)&Qg[r * 64 + s * 16];
    }
    for (int idx = tid; idx < 4096; idx += 256) {
        int r = idx >> 2, s = idx & 3;
        *(int4*)&Ksm[r * 80 + s * 16] = *(const int4*)&Kg[r * 64 + s * 16];
    }
    for (int idx = tid; idx < 4096; idx += 256) {
        int r = idx >> 6, s = idx & 63;
        *(int4*)&Vsm[r * 1040 + s * 16] = *(const int4*)&Vg[r * 1024 + s * 16];
    }
    if (tid < 128) rs[tid] = 0.f;
    __syncthreads();

    float s6 = g_sc[6];

    // ---------- pass 1: row sums of the exp2 numerator ----------
    for (int c = 0; c < 8; c++) {
        int acc[4][4][4] = {};
        #pragma unroll
        for (int ks = 0; ks < 64; ks += 32) {
            uint32_t bf[4][2];
            #pragma unroll
            for (int j = 0; j < 4; j++) {
                const int8_t* bp = &Ksm[(c * 128 + wc * 32 + j * 8 + g) * 80 + ks + q4 * 4];
                bf[j][0] = *(const uint32_t*)bp;
                bf[j][1] = *(const uint32_t*)(bp + 16);
            }
            #pragma unroll
            for (int i = 0; i < 4; i++) {
                const int8_t* ap0 = &Qsm[(wr * 64 + i * 16 + g) * 80 + ks + q4 * 4];
                uint32_t a0 = *(const uint32_t*)ap0;
                uint32_t a2 = *(const uint32_t*)(ap0 + 16);
                const int8_t* ap1 = ap0 + 8 * 80;
                uint32_t a1 = *(const uint32_t*)ap1;
                uint32_t a3 = *(const uint32_t*)(ap1 + 16);
                #pragma unroll
                for (int j = 0; j < 4; j++) {
                    asm volatile(
                        "mma.sync.aligned.m16n8k32.row.col.s32.s8.s8.s32 "
                        "{%0,%1,%2,%3},{%4,%5,%6,%7},{%8,%9},{%0,%1,%2,%3};"
                        : "+r"(acc[i][j][0]), "+r"(acc[i][j][1]),
                          "+r"(acc[i][j][2]), "+r"(acc[i][j][3])
                        : "r"(a0), "r"(a1), "r"(a2), "r"(a3),
                          "r"(bf[j][0]), "r"(bf[j][1]));
                }
            }
        }
        #pragma unroll
        for (int i = 0; i < 4; i++) {
            #pragma unroll
            for (int part = 0; part < 2; part++) {
                float p = 0.f;
                #pragma unroll
                for (int j = 0; j < 4; j++) {
                    #pragma unroll
                    for (int vp = 0; vp < 2; vp++) {
                        float e = s6 * (float)acc[i][j][part * 2 + vp];
                        float f = floorf(e);
                        p += exp2f(f) * (1.0f + (e - f));
                    }
                }
                p += __shfl_xor_sync(0xffffffffu, p, 1);
                p += __shfl_xor_sync(0xffffffffu, p, 2);
                if (q4 == 0) atomicAdd(&rs[wr * 64 + i * 16 + g + part * 8], p);
            }
        }
    }
    __syncthreads();
    if (tid < 128) rs[tid] = 1.0f / (rs[tid] * g_sc[4]);  // 1/(sum*am)
    __syncthreads();

    // ---------- pass 2: recompute, quantize attn, PV MMA ----------
    int pv[4][2][4] = {};
    for (int c = 0; c < 8; c++) {
        int acc[4][4][4] = {};
        #pragma unroll
        for (int ks = 0; ks < 64; ks += 32) {
            uint32_t bf[4][2];
            #pragma unroll
            for (int j = 0; j < 4; j++) {
                const int8_t* bp = &Ksm[(c * 128 + wc * 32 + j * 8 + g) * 80 + ks + q4 * 4];
                bf[j][0] = *(const uint32_t*)bp;
                bf[j][1] = *(const uint32_t*)(bp + 16);
            }
            #pragma unroll
            for (int i = 0; i < 4; i++) {
                const int8_t* ap0 = &Qsm[(wr * 64 + i * 16 + g) * 80 + ks + q4 * 4];
                uint32_t a0 = *(const uint32_t*)ap0;
                uint32_t a2 = *(const uint32_t*)(ap0 + 16);
                const int8_t* ap1 = ap0 + 8 * 80;
                uint32_t a1 = *(const uint32_t*)ap1;
                uint32_t a3 = *(const uint32_t*)(ap1 + 16);
                #pragma unroll
                for (int j = 0; j < 4; j++) {
                    asm volatile(
                        "mma.sync.aligned.m16n8k32.row.col.s32.s8.s8.s32 "
                        "{%0,%1,%2,%3},{%4,%5,%6,%7},{%8,%9},{%0,%1,%2,%3};"
                        : "+r"(acc[i][j][0]), "+r"(acc[i][j][1]),
                          "+r"(acc[i][j][2]), "+r"(acc[i][j][3])
                        : "r"(a0), "r"(a1), "r"(a2), "r"(a3),
                          "r"(bf[j][0]), "r"(bf[j][1]));
                }
            }
        }
        // quantize attn chunk into smem
        #pragma unroll
        for (int i = 0; i < 4; i++) {
            #pragma unroll
            for (int part = 0; part < 2; part++) {
                int row = wr * 64 + i * 16 + g + part * 8;
                float iv = rs[row];
                #pragma unroll
                for (int j = 0; j < 4; j++) {
                    float e0 = s6 * (float)acc[i][j][part * 2 + 0];
                    float f0 = floorf(e0);
                    float p0 = exp2f(f0) * (1.0f + (e0 - f0));
                    float e1 = s6 * (float)acc[i][j][part * 2 + 1];
                    float f1 = floorf(e1);
                    float p1 = exp2f(f1) * (1.0f + (e1 - f1));
                    uint8_t v0 = (uint8_t)q8(p0 * iv);
                    uint8_t v1 = (uint8_t)q8(p1 * iv);
                    uint16_t pk = (uint16_t)v0 | ((uint16_t)v1 << 8);
                    *(uint16_t*)&Asm[row * 144 + wc * 32 + j * 8 + q4 * 2] = pk;
                }
            }
        }
        __syncthreads();
        // PV: attn(128x128) @ Vchunk(128 x 64) ; warp tile 64x16
        #pragma unroll
        for (int ks = 0; ks < 128; ks += 32) {
            uint32_t bf[2][2];
            #pragma unroll
            for (int j = 0; j < 2; j++) {
                const int8_t* bp = &Vsm[(wc * 16 + j * 8 + g) * 1040 + c * 128 + ks + q4 * 4];
                bf[j][0] = *(const uint32_t*)bp;
                bf[j][1] = *(const uint32_t*)(bp + 16);
            }
            #pragma unroll
            for (int i = 0; i < 4; i++) {
                const int8_t* ap0 = &Asm[(wr * 64 + i * 16 + g) * 144 + ks + q4 * 4];
                uint32_t a0 = *(const uint32_t*)ap0;
                uint32_t a2 = *(const uint32_t*)(ap0 + 16);
                const int8_t* ap1 = ap0 + 8 * 144;
                uint32_t a1 = *(const uint32_t*)ap1;
                uint32_t a3 = *(const uint32_t*)(ap1 + 16);
                #pragma unroll
                for (int j = 0; j < 2; j++) {
                    asm volatile(
                        "mma.sync.aligned.m16n8k32.row.col.s32.s8.s8.s32 "
                        "{%0,%1,%2,%3},{%4,%5,%6,%7},{%8,%9},{%0,%1,%2,%3};"
                        : "+r"(pv[i][j][0]), "+r"(pv[i][j][1]),
                          "+r"(pv[i][j][2]), "+r"(pv[i][j][3])
                        : "r"(a0), "r"(a1), "r"(a2), "r"(a3),
                          "r"(bf[j][0]), "r"(bf[j][1]));
                }
            }
        }
        __syncthreads();
    }

    // epilogue: quantize x1 and scatter into g_x1q
    float s7 = g_sc[7], s5 = g_sc[5];
    #pragma unroll
    for (int i = 0; i < 4; i++) {
        #pragma unroll
        for (int j = 0; j < 2; j++) {
            #pragma unroll
            for (int v = 0; v < 4; v++) {
                int rr = qBase + wr * 64 + i * 16 + g + (v >> 1) * 8;
                int cc = wc * 16 + j * 8 + q4 * 2 + (v & 1);
                float x = (float)pv[i][j][v] * s7 / s5;
                g_x1q[((long)(b * SEQ + rr)) * CH + h * HDIM + cc] = q8(x);
            }
        }
    }
}

// ---------------- int8 MMA GEMM for qkv / proj ----------------
// MODE 0: qkv  (out=g_qkv int32 + bias)
// MODE 3: proj (out=d_out fp32, scale+bias epilogue)
template <int MODE>
__global__ void gemm_s8(float* __restrict__ outf,
                        const float* __restrict__ e1, const float* __restrict__ e2) {
    constexpr int K  = 768;
    constexpr int BM = 128, BN = 128, BK = 64;
    constexpr int WR = 2, WC = 4;
    constexpr int NWARP = WR * WC;
    constexpr int NTHR  = NWARP * 32;
    constexpr int WM = BM / WR, WN = BN / WC;
    constexpr int MI = WM / 16, NI = WN / 8;
    constexpr int SAS = BK + 16;

    __shared__ __align__(16) int8_t As[BM * SAS];
    __shared__ __align__(16) int8_t Bs[BN * SAS];

    const int8_t* A  = (MODE == 0) ? g_x0q  : g_x1q;
    const int8_t* Bw = (MODE == 0) ? g_wqkv : g_wproj;
    constexpr int NCOL = (MODE == 0) ? C3v : CH;

    int tid = threadIdx.x;
    int warp = tid >> 5, lane = tid & 31;
    int wr = warp / WC, wc = warp % WC;
    int g = lane >> 2, q4 = lane & 3;
    int rowBase = blockIdx.y * BM;
    int colBase = blockIdx.x * BN;

    int acc[MI][NI][4];
    #pragma unroll
    for (int i = 0; i < MI; i++)
        #pragma unroll
        for (int j = 0; j < NI; j++)
            #pragma unroll
            for (int v = 0; v < 4; v++) acc[i][j][v] = 0;

    for (int k0 = 0; k0 < K; k0 += BK) {
        constexpr int AV = BM * BK / 16;
        #pragma unroll
        for (int idx = tid; idx < AV; idx += NTHR) {
            int r = idx / (BK / 16), seg = idx % (BK / 16);
            *(int4*)&As[r * SAS + seg * 16] =
                *(const int4*)&A[(long)(rowBase + r) * K + k0 + seg * 16];
        }
        constexpr int BV = BN * BK / 16;
        #pragma unroll
        for (int idx = tid; idx < BV; idx += NTHR) {
            int r = idx / (BK / 16), seg = idx % (BK / 16);
            *(int4*)&Bs[r * SAS + seg * 16] =
                *(const int4*)&Bw[(long)(colBase + r) * K + k0 + seg * 16];
        }
        __syncthreads();

        #pragma unroll
        for (int ks = 0; ks < BK; ks += 32) {
            uint32_t bf[NI][2];
            #pragma unroll
            for (int j = 0; j < NI; j++) {
                const int8_t* bp = &Bs[(wc * WN + j * 8 + g) * SAS + ks + q4 * 4];
                bf[j][0] = *(const uint32_t*)bp;
                bf[j][1] = *(const uint32_t*)(bp + 16);
            }
            #pragma unroll
            for (int i = 0; i < MI; i++) {
                const int8_t* ap0 = &As[(wr * WM + i * 16 + g) * SAS + ks + q4 * 4];
                uint32_t a0 = *(const uint32_t*)ap0;
                uint32_t a2 = *(const uint32_t*)(ap0 + 16);
                const int8_t* ap1 = ap0 + 8 * SAS;
                uint32_t a1 = *(const uint32_t*)ap1;
                uint32_t a3 = *(const uint32_t*)(ap1 + 16);
                #pragma unroll
                for (int j = 0; j < NI; j++) {
                    asm volatile(
                        "mma.sync.aligned.m16n8k32.row.col.s32.s8.s8.s32 "
                        "{%0,%1,%2,%3},{%4,%5,%6,%7},{%8,%9},{%0,%1,%2,%3};"
                        : "+r"(acc[i][j][0]), "+r"(acc[i][j][1]),
                          "+r"(acc[i][j][2]), "+r"(acc[i][j][3])
                        : "r"(a0), "r"(a1), "r"(a2), "r"(a3),
                          "r"(bf[j][0]), "r"(bf[j][1]));
                }
            }
        }
        __syncthreads();
    }

    float s5 = g_sc[5];
    int rb = rowBase + wr * WM;
    int cb = colBase + wc * WN;
    #pragma unroll
    for (int i = 0; i < MI; i++) {
        #pragma unroll
        for (int j = 0; j < NI; j++) {
            #pragma unroll
            for (int v = 0; v < 4; v++) {
                int rr = rb + i * 16 + g + (v >> 1) * 8;
                int cc = cb + j * 8 + q4 * 2 + (v & 1);
                int a = acc[i][j][v];
                if constexpr (MODE == 0) {
                    g_qkv[(long)rr * NCOL + cc] = a + g_biasi[cc];
                } else {
                    outf[(long)rr * NCOL + cc] = ((float)a * e1[cc]) * s5 + e2[cc];
                }
            }
        }
    }
}

// ---------------- launcher ----------------
extern "C" void kernel_launch(void* const* d_in, const int* in_sizes, int n_in,
                              void* d_out, int out_size) {
    const float* x0             = (const float*)d_in[0];
    const float* qkv_w          = (const float*)d_in[1];
    const float* qkv_b          = (const float*)d_in[2];
    const float* qkv_alpha      = (const float*)d_in[3];
    const float* qkv_act_alpha  = (const float*)d_in[4];
    const float* proj_w         = (const float*)d_in[5];
    const float* proj_b         = (const float*)d_in[6];
    const float* proj_alpha     = (const float*)d_in[7];
    const float* proj_act_alpha = (const float*)d_in[8];
    const float* norm_q_w       = (const float*)d_in[9];
    const float* norm_q_b       = (const float*)d_in[10];
    const float* norm_k_w       = (const float*)d_in[11];
    const float* norm_k_b       = (const float*)d_in[12];
    const float* q_alpha        = (const float*)d_in[13];
    const float* k_alpha        = (const float*)d_in[14];
    const float* v_alpha        = (const float*)d_in[15];
    const float* attn_alpha     = (const float*)d_in[16];
    float* out = (float*)d_out;

    cudaFuncSetAttribute(k_attn_fused, cudaFuncAttributeMaxDynamicSharedMemorySize, SMEM_FUSED);

    k_scalars<<<1, 256>>>(qkv_act_alpha, proj_act_alpha, q_alpha, k_alpha, v_alpha, attn_alpha);
    k_quant_x0<<<(ROWS * CH + 255) / 256, 256>>>(x0);
    k_quant_wqkv<<<(C3v * CH + 255) / 256, 256>>>(qkv_w, qkv_alpha, qkv_b);
    k_quant_wproj<<<(CH * CH + 255) / 256, 256>>>(proj_w, proj_alpha);

    // QKV GEMM: 4096 x 2304 x 768
    gemm_s8<0><<<dim3(C3v / 128, ROWS / 128, 1), 256>>>(nullptr, nullptr, nullptr);

    // per-row integer mean/var + quantization
    k_norm<<<dim3(SEQ / 64, 1, NBH), 64>>>(qkv_alpha, norm_q_w, norm_q_b, norm_k_w, norm_k_b);

    // fused QK -> exp2-softmax -> quantize -> PV
    k_attn_fused<<<dim3(SEQ / 128, NBH), 256, SMEM_FUSED>>>();

    // projection GEMM: 4096 x 768 x 768, fp32 epilogue to d_out
    gemm_s8<3><<<dim3(CH / 128, ROWS / 128, 1), 256>>>(out, proj_alpha, proj_b);
}

// round 3
// speedup vs baseline: 1.1749x; 1.1386x over previous
#include <cuda_runtime.h>
#include <stdint.h>

// ---------------- problem constants ----------------
constexpr int BATCH = 4, SEQ = 1024, CH = 768, HEADS = 12, HDIM = 64;
constexpr int ROWS = BATCH * SEQ;   // 4096
constexpr int C3v  = 3 * CH;        // 2304
constexpr int NBH  = BATCH * HEADS; // 48

// ---------------- scratch (__device__ globals; no runtime alloc) ----------------
__device__ __align__(256) int8_t g_x0q [ROWS * CH];
__device__ __align__(256) int8_t g_wqkv[C3v * CH];
__device__            int    g_biasi[C3v];
__device__ __align__(256) int8_t g_wproj[CH * CH];
__device__ __align__(256) float  g_rw  [C3v + CH];              // reciprocals of alphas
__device__ __align__(256) int    g_qkv [ROWS * C3v];            // 37.7 MB
__device__ __align__(256) int8_t g_q2  [NBH * SEQ * HDIM];
__device__ __align__(256) int8_t g_k2  [NBH * SEQ * HDIM];
__device__ __align__(256) int8_t g_v2t [NBH * HDIM * SEQ];      // transposed V
__device__ __align__(256) int8_t g_x1q [ROWS * CH];
// 0:a_in 1:aq 2:ak 3:av 4:am 5:ap 6:LOG2E*hs*aq*ak 7:am*av 8:1/a_in 9:(am*av)/ap
__device__            float  g_sc[12];

__device__ __forceinline__ float clip8(float x) { return fminf(fmaxf(x, -8.f), 7.f); }
__device__ __forceinline__ int8_t q8(float x) { return (int8_t)(int)rintf(clip8(x)); }

// 2^floor(e) * (1 + frac(e)) — exact IEEE construction, valid for e > -126.
__device__ __forceinline__ float pexp2(float e) {
    return __int_as_float((int)((e + 127.0f) * 8388608.0f));
}

__device__ __forceinline__ void cp16(void* dst, const void* src) {
    uint32_t d = (uint32_t)__cvta_generic_to_shared(dst);
    asm volatile("cp.async.cg.shared.global [%0], [%1], 16;" :: "r"(d), "l"(src));
}
#define CP_COMMIT() asm volatile("cp.async.commit_group;")
#define CP_WAIT1()  asm volatile("cp.async.wait_group 1;")
#define CP_WAIT0()  asm volatile("cp.async.wait_group 0;")

// ---------------- scalar means ----------------
__global__ void k_scalars(const float* __restrict__ qkv_act_alpha,
                          const float* __restrict__ proj_act_alpha,
                          const float* __restrict__ q_alpha,
                          const float* __restrict__ k_alpha,
                          const float* __restrict__ v_alpha,
                          const float* __restrict__ attn_alpha) {
    __shared__ float sh[256];
    int t = threadIdx.x;
    float s = 0.f;
    for (int i = t; i < CH; i += 256) s += qkv_act_alpha[i];
    sh[t] = s; __syncthreads();
    for (int o = 128; o > 0; o >>= 1) { if (t < o) sh[t] += sh[t + o]; __syncthreads(); }
    float a_in = sh[0] / (float)CH;
    __syncthreads();
    s = 0.f;
    for (int i = t; i < CH; i += 256) s += proj_act_alpha[i];
    sh[t] = s; __syncthreads();
    for (int o = 128; o > 0; o >>= 1) { if (t < o) sh[t] += sh[t + o]; __syncthreads(); }
    float ap = sh[0] / (float)CH;
    if (t == 0) {
        float aq = 0.f, ak = 0.f, av = 0.f, am = 0.f;
        for (int i = 0; i < HEADS; i++) { aq += q_alpha[i]; ak += k_alpha[i]; av += v_alpha[i]; am += attn_alpha[i]; }
        aq /= HEADS; ak /= HEADS; av /= HEADS; am /= HEADS;
        g_sc[0] = a_in; g_sc[1] = aq; g_sc[2] = ak; g_sc[3] = av; g_sc[4] = am; g_sc[5] = ap;
        g_sc[6] = 1.4426950408889634f * ((0.125f * aq) * ak);
        g_sc[7] = am * av;
        g_sc[8] = 1.0f / a_in;
        g_sc[9] = (am * av) / ap;
    }
}

// reciprocals of qkv_alpha (3C) and proj_alpha (C)
__global__ void k_recips(const float* __restrict__ qkv_alpha,
                         const float* __restrict__ proj_alpha) {
    int i = blockIdx.x * blockDim.x + threadIdx.x;
    if (i < C3v) g_rw[i] = 1.0f / qkv_alpha[i];
    else if (i < C3v + CH) g_rw[i] = 1.0f / proj_alpha[i - C3v];
}

// ---------------- quantizers (multiply by precomputed reciprocal) ----------------
__global__ void k_quant_x0(const float* __restrict__ x0) {
    int i = blockIdx.x * blockDim.x + threadIdx.x;
    float inv = g_sc[8];
    if (i < ROWS * CH) g_x0q[i] = q8(x0[i] * inv);
}
__global__ void k_quant_wqkv(const float* __restrict__ w, const float* __restrict__ alpha,
                             const float* __restrict__ bvec) {
    int i = blockIdx.x * blockDim.x + threadIdx.x;
    if (i < C3v * CH) {
        int o = i / CH;
        g_wqkv[i] = q8(w[i] * g_rw[o]);
        if ((i % CH) == 0) g_biasi[o] = (int)truncf(bvec[o] / g_sc[0] / alpha[o]);
    }
}
__global__ void k_quant_wproj(const float* __restrict__ w) {
    int i = blockIdx.x * blockDim.x + threadIdx.x;
    if (i < CH * CH) {
        int o = i / CH;
        g_wproj[i] = q8(w[i] * g_rw[C3v + o]);
    }
}

// ---------------- integer mean/var norm + q/k/v quantization ----------------
// grid (SEQ/128, 1, NBH), 128 threads; thread t owns row n0+t of head (b,h).
__global__ void __launch_bounds__(128) k_norm(
        const float* __restrict__ qkv_alpha,
        const float* __restrict__ nqw, const float* __restrict__ nqb,
        const float* __restrict__ nkw, const float* __restrict__ nkb) {
    int bh = blockIdx.z, b = bh / HEADS, h = bh % HEADS;
    int n0 = blockIdx.x * 128;
    int t = threadIdx.x;
    __shared__ int sm[128][65];
    __shared__ float alq[64], alk[64], alvs[64];
    __shared__ float boWq[64], woaq[64], boWk[64], woak[64];
    __shared__ int coef[64];
    if (t < 64) {
        alq[t]  = qkv_alpha[h * HDIM + t];
        alk[t]  = qkv_alpha[CH + h * HDIM + t];
        alvs[t] = (g_sc[0] * qkv_alpha[2 * CH + h * HDIM + t]) / g_sc[3];
        float wq = nqw[t], wk = nkw[t];
        boWq[t] = nqb[t] / wq;  woaq[t] = wq / g_sc[1];
        boWk[t] = nkb[t] / wk;  woak[t] = wk / g_sc[2];
        coef[t] = 1024 / (t + 1);
    }
    __syncthreads();

    const long rowg = (long)(b * SEQ + n0);

    // ---- Q branch ----
    #pragma unroll 4
    for (int idx = t; idx < 128 * 64; idx += 128) {
        int r = idx >> 6, c = idx & 63;
        sm[r][c] = g_qkv[(rowg + r) * C3v + h * HDIM + c];
    }
    __syncthreads();
    {
        int m = 0, vv = 0;
        #pragma unroll 8
        for (int d = 0; d < HDIM; d++) {
            float xf = (float)sm[t][d] * alq[d];
            int xi = (int)xf;
            int dd = xi - m;
            m += (dd * coef[d]) >> 10;
            vv += dd * (xi - m);
        }
        float mu = (float)m;
        float invden = 1.0f / (sqrtf((float)vv * 0.015625f) + 1e-5f);
        int8_t* outq = g_q2 + ((long)bh * SEQ + n0 + t) * HDIM;
        #pragma unroll 8
        for (int d = 0; d < HDIM; d++) {
            float xf = (float)sm[t][d] * alq[d];
            float q1 = (xf - mu) * invden;
            outq[d] = q8((q1 + boWq[d]) * woaq[d]);
        }
    }
    __syncthreads();

    // ---- K branch ----
    #pragma unroll 4
    for (int idx = t; idx < 128 * 64; idx += 128) {
        int r = idx >> 6, c = idx & 63;
        sm[r][c] = g_qkv[(rowg + r) * C3v + CH + h * HDIM + c];
    }
    __syncthreads();
    {
        int m = 0, vv = 0;
        #pragma unroll 8
        for (int d = 0; d < HDIM; d++) {
            float xf = (float)sm[t][d] * alk[d];
            int xi = (int)xf;
            int dd = xi - m;
            m += (dd * coef[d]) >> 10;
            vv += dd * (xi - m);
        }
        float mu = (float)m;
        float invden = 1.0f / (sqrtf((float)vv * 0.015625f) + 1e-5f);
        int8_t* outk = g_k2 + ((long)bh * SEQ + n0 + t) * HDIM;
        #pragma unroll 8
        for (int d = 0; d < HDIM; d++) {
            float xf = (float)sm[t][d] * alk[d];
            float k1 = (xf - mu) * invden;
            outk[d] = q8((k1 + boWk[d]) * woak[d]);
        }
    }
    __syncthreads();

    // ---- V branch (write transposed) ----
    #pragma unroll 4
    for (int idx = t; idx < 128 * 64; idx += 128) {
        int r = idx >> 6, c = idx & 63;
        sm[r][c] = g_qkv[(rowg + r) * C3v + 2 * CH + h * HDIM + c];
    }
    __syncthreads();
    {
        int8_t* outv = g_v2t + (long)bh * HDIM * SEQ + n0 + t;
        #pragma unroll 8
        for (int d = 0; d < HDIM; d++)
            outv[d * SEQ] = q8((float)sm[t][d] * alvs[d]);
    }
}

// ---------------- fused flash-style attention ----------------
constexpr int OFF_K = 0;
constexpr int OFF_V = 81920;
constexpr int OFF_Q = 148480;
constexpr int OFF_A = 158720;
constexpr int OFF_S = 177152;
constexpr int SMEM_FUSED = 177664;

__global__ void __launch_bounds__(256, 1) k_attn_fused() {
    extern __shared__ __align__(16) int8_t sh[];
    int8_t* Ksm = sh + OFF_K;
    int8_t* Vsm = sh + OFF_V;
    int8_t* Qsm = sh + OFF_Q;
    int8_t* Asm = sh + OFF_A;
    float*  rs  = (float*)(sh + OFF_S);

    int bh = blockIdx.y, b = bh / HEADS, h = bh % HEADS;
    int qBase = blockIdx.x * 128;
    int tid = threadIdx.x, warp = tid >> 5, lane = tid & 31;
    int g = lane >> 2, q4 = lane & 3;
    int wr = warp >> 2, wc = warp & 3;

    const int8_t* Qg = g_q2 + ((long)bh * SEQ + qBase) * HDIM;
    const int8_t* Kg = g_k2 + (long)bh * SEQ * HDIM;
    const int8_t* Vg = g_v2t + (long)bh * HDIM * SEQ;

    for (int idx = tid; idx < 512; idx += 256) {
        int r = idx >> 2, s = idx & 3;
        cp16(&Qsm[r * 80 + s * 16], &Qg[r * 64 + s * 16]);
    }
    for (int idx = tid; idx < 4096; idx += 256) {
        int r = idx >> 2, s = idx & 3;
        cp16(&Ksm[r * 80 + s * 16], &Kg[r * 64 + s * 16]);
    }
    for (int idx = tid; idx < 4096; idx += 256) {
        int r = idx >> 6, s = idx & 63;
        cp16(&Vsm[r * 1040 + s * 16], &Vg[r * 1024 + s * 16]);
    }
    CP_COMMIT();
    if (tid < 128) rs[tid] = 0.f;
    CP_WAIT0();
    __syncthreads();

    float s6 = g_sc[6];

    // ---------- pass 1: row sums of the exp2 numerator ----------
    for (int c = 0; c < 8; c++) {
        int acc[4][4][4] = {};
        #pragma unroll
        for (int ks = 0; ks < 64; ks += 32) {
            uint32_t bf[4][2];
            #pragma unroll
            for (int j = 0; j < 4; j++) {
                const int8_t* bp = &Ksm[(c * 128 + wc * 32 + j * 8 + g) * 80 + ks + q4 * 4];
                bf[j][0] = *(const uint32_t*)bp;
                bf[j][1] = *(const uint32_t*)(bp + 16);
            }
            #pragma unroll
            for (int i = 0; i < 4; i++) {
                const int8_t* ap0 = &Qsm[(wr * 64 + i * 16 + g) * 80 + ks + q4 * 4];
                uint32_t a0 = *(const uint32_t*)ap0;
                uint32_t a2 = *(const uint32_t*)(ap0 + 16);
                const int8_t* ap1 = ap0 + 8 * 80;
                uint32_t a1 = *(const uint32_t*)ap1;
                uint32_t a3 = *(const uint32_t*)(ap1 + 16);
                #pragma unroll
                for (int j = 0; j < 4; j++) {
                    asm volatile(
                        "mma.sync.aligned.m16n8k32.row.col.s32.s8.s8.s32 "
                        "{%0,%1,%2,%3},{%4,%5,%6,%7},{%8,%9},{%0,%1,%2,%3};"
                        : "+r"(acc[i][j][0]), "+r"(acc[i][j][1]),
                          "+r"(acc[i][j][2]), "+r"(acc[i][j][3])
                        : "r"(a0), "r"(a1), "r"(a2), "r"(a3),
                          "r"(bf[j][0]), "r"(bf[j][1]));
                }
            }
        }
        #pragma unroll
        for (int i = 0; i < 4; i++) {
            #pragma unroll
            for (int part = 0; part < 2; part++) {
                float p = 0.f;
                #pragma unroll
                for (int j = 0; j < 4; j++) {
                    #pragma unroll
                    for (int vp = 0; vp < 2; vp++)
                        p += pexp2(s6 * (float)acc[i][j][part * 2 + vp]);
                }
                p += __shfl_xor_sync(0xffffffffu, p, 1);
                p += __shfl_xor_sync(0xffffffffu, p, 2);
                if (q4 == 0) atomicAdd(&rs[wr * 64 + i * 16 + g + part * 8], p);
            }
        }
    }
    __syncthreads();
    if (tid < 128) rs[tid] = 1.0f / (rs[tid] * g_sc[4]);
    __syncthreads();

    // ---------- pass 2: recompute, quantize attn, PV MMA ----------
    int pv[4][2][4] = {};
    for (int c = 0; c < 8; c++) {
        int acc[4][4][4] = {};
        #pragma unroll
        for (int ks = 0; ks < 64; ks += 32) {
            uint32_t bf[4][2];
            #pragma unroll
            for (int j = 0; j < 4; j++) {
                const int8_t* bp = &Ksm[(c * 128 + wc * 32 + j * 8 + g) * 80 + ks + q4 * 4];
                bf[j][0] = *(const uint32_t*)bp;
                bf[j][1] = *(const uint32_t*)(bp + 16);
            }
            #pragma unroll
            for (int i = 0; i < 4; i++) {
                const int8_t* ap0 = &Qsm[(wr * 64 + i * 16 + g) * 80 + ks + q4 * 4];
                uint32_t a0 = *(const uint32_t*)ap0;
                uint32_t a2 = *(const uint32_t*)(ap0 + 16);
                const int8_t* ap1 = ap0 + 8 * 80;
                uint32_t a1 = *(const uint32_t*)ap1;
                uint32_t a3 = *(const uint32_t*)(ap1 + 16);
                #pragma unroll
                for (int j = 0; j < 4; j++) {
                    asm volatile(
                        "mma.sync.aligned.m16n8k32.row.col.s32.s8.s8.s32 "
                        "{%0,%1,%2,%3},{%4,%5,%6,%7},{%8,%9},{%0,%1,%2,%3};"
                        : "+r"(acc[i][j][0]), "+r"(acc[i][j][1]),
                          "+r"(acc[i][j][2]), "+r"(acc[i][j][3])
                        : "r"(a0), "r"(a1), "r"(a2), "r"(a3),
                          "r"(bf[j][0]), "r"(bf[j][1]));
                }
            }
        }
        #pragma unroll
        for (int i = 0; i < 4; i++) {
            #pragma unroll
            for (int part = 0; part < 2; part++) {
                int row = wr * 64 + i * 16 + g + part * 8;
                float iv = rs[row];
                #pragma unroll
                for (int j = 0; j < 4; j++) {
                    float p0 = pexp2(s6 * (float)acc[i][j][part * 2 + 0]);
                    float p1 = pexp2(s6 * (float)acc[i][j][part * 2 + 1]);
                    uint8_t v0 = (uint8_t)q8(p0 * iv);
                    uint8_t v1 = (uint8_t)q8(p1 * iv);
                    uint16_t pk = (uint16_t)v0 | ((uint16_t)v1 << 8);
                    *(uint16_t*)&Asm[row * 144 + wc * 32 + j * 8 + q4 * 2] = pk;
                }
            }
        }
        __syncthreads();
        #pragma unroll
        for (int ks = 0; ks < 128; ks += 32) {
            uint32_t bf[2][2];
            #pragma unroll
            for (int j = 0; j < 2; j++) {
                const int8_t* bp = &Vsm[(wc * 16 + j * 8 + g) * 1040 + c * 128 + ks + q4 * 4];
                bf[j][0] = *(const uint32_t*)bp;
                bf[j][1] = *(const uint32_t*)(bp + 16);
            }
            #pragma unroll
            for (int i = 0; i < 4; i++) {
                const int8_t* ap0 = &Asm[(wr * 64 + i * 16 + g) * 144 + ks + q4 * 4];
                uint32_t a0 = *(const uint32_t*)ap0;
                uint32_t a2 = *(const uint32_t*)(ap0 + 16);
                const int8_t* ap1 = ap0 + 8 * 144;
                uint32_t a1 = *(const uint32_t*)ap1;
                uint32_t a3 = *(const uint32_t*)(ap1 + 16);
                #pragma unroll
                for (int j = 0; j < 2; j++) {
                    asm volatile(
                        "mma.sync.aligned.m16n8k32.row.col.s32.s8.s8.s32 "
                        "{%0,%1,%2,%3},{%4,%5,%6,%7},{%8,%9},{%0,%1,%2,%3};"
                        : "+r"(pv[i][j][0]), "+r"(pv[i][j][1]),
                          "+r"(pv[i][j][2]), "+r"(pv[i][j][3])
                        : "r"(a0), "r"(a1), "r"(a2), "r"(a3),
                          "r"(bf[j][0]), "r"(bf[j][1]));
                }
            }
        }
        __syncthreads();
    }

    // epilogue: quantize x1 and scatter into g_x1q
    float r9 = g_sc[9];
    #pragma unroll
    for (int i = 0; i < 4; i++) {
        #pragma unroll
        for (int j = 0; j < 2; j++) {
            #pragma unroll
            for (int v = 0; v < 4; v++) {
                int rr = qBase + wr * 64 + i * 16 + g + (v >> 1) * 8;
                int cc = wc * 16 + j * 8 + q4 * 2 + (v & 1);
                float x = (float)pv[i][j][v] * r9;
                g_x1q[((long)(b * SEQ + rr)) * CH + h * HDIM + cc] = q8(x);
            }
        }
    }
}

// ---------------- int8 MMA GEMM for qkv / proj (cp.async 2-stage pipeline) ----------------
template <int MODE>
__global__ void __launch_bounds__(256) gemm_s8(float* __restrict__ outf,
                        const float* __restrict__ e1, const float* __restrict__ e2) {
    constexpr int K  = 768;
    constexpr int BM = 128, BN = 128, BK = 64;
    constexpr int NTHR = 256;
    constexpr int WM = 64, WN = 32;
    constexpr int MI = 4, NI = 4;
    constexpr int SAS = BK + 16;
    constexpr int NK = K / BK;  // 12

    __shared__ __align__(16) int8_t As[2][BM * SAS];
    __shared__ __align__(16) int8_t Bs[2][BN * SAS];

    const int8_t* A  = (MODE == 0) ? g_x0q  : g_x1q;
    const int8_t* Bw = (MODE == 0) ? g_wqkv : g_wproj;
    constexpr int NCOL = (MODE == 0) ? C3v : CH;

    int tid = threadIdx.x;
    int warp = tid >> 5, lane = tid & 31;
    int wr = warp / 4, wc = warp % 4;
    int g = lane >> 2, q4 = lane & 3;
    int rowBase = blockIdx.y * BM;
    int colBase = blockIdx.x * BN;

    auto load_stage = [&](int st, int k0) {
        #pragma unroll
        for (int idx = tid; idx < BM * BK / 16; idx += NTHR) {
            int r = idx / (BK / 16), seg = idx % (BK / 16);
            cp16(&As[st][r * SAS + seg * 16],
                 &A[(long)(rowBase + r) * K + k0 + seg * 16]);
        }
        #pragma unroll
        for (int idx = tid; idx < BN * BK / 16; idx += NTHR) {
            int r = idx / (BK / 16), seg = idx % (BK / 16);
            cp16(&Bs[st][r * SAS + seg * 16],
                 &Bw[(long)(colBase + r) * K + k0 + seg * 16]);
        }
    };

    int acc[MI][NI][4];
    #pragma unroll
    for (int i = 0; i < MI; i++)
        #pragma unroll
        for (int j = 0; j < NI; j++)
            #pragma unroll
            for (int v = 0; v < 4; v++) acc[i][j][v] = 0;

    load_stage(0, 0);
    CP_COMMIT();

    for (int it = 0; it < NK; it++) {
        int cur = it & 1;
        if (it + 1 < NK) {
            load_stage(cur ^ 1, (it + 1) * BK);
            CP_COMMIT();
            CP_WAIT1();
        } else {
            CP_WAIT0();
        }
        __syncthreads();

        #pragma unroll
        for (int ks = 0; ks < BK; ks += 32) {
            uint32_t bf[NI][2];
            #pragma unroll
            for (int j = 0; j < NI; j++) {
                const int8_t* bp = &Bs[cur][(wc * WN + j * 8 + g) * SAS + ks + q4 * 4];
                bf[j][0] = *(const uint32_t*)bp;
                bf[j][1] = *(const uint32_t*)(bp + 16);
            }
            #pragma unroll
            for (int i = 0; i < MI; i++) {
                const int8_t* ap0 = &As[cur][(wr * WM + i * 16 + g) * SAS + ks + q4 * 4];
                uint32_t a0 = *(const uint32_t*)ap0;
                uint32_t a2 = *(const uint32_t*)(ap0 + 16);
                const int8_t* ap1 = ap0 + 8 * SAS;
                uint32_t a1 = *(const uint32_t*)ap1;
                uint32_t a3 = *(const uint32_t*)(ap1 + 16);
                #pragma unroll
                for (int j = 0; j < NI; j++) {
                    asm volatile(
                        "mma.sync.aligned.m16n8k32.row.col.s32.s8.s8.s32 "
                        "{%0,%1,%2,%3},{%4,%5,%6,%7},{%8,%9},{%0,%1,%2,%3};"
                        : "+r"(acc[i][j][0]), "+r"(acc[i][j][1]),
                          "+r"(acc[i][j][2]), "+r"(acc[i][j][3])
                        : "r"(a0), "r"(a1), "r"(a2), "r"(a3),
                          "r"(bf[j][0]), "r"(bf[j][1]));
                }
            }
        }
        __syncthreads();
    }

    float s5 = g_sc[5];
    int rb = rowBase + wr * WM;
    int cb = colBase + wc * WN;
    #pragma unroll
    for (int i = 0; i < MI; i++) {
        #pragma unroll
        for (int j = 0; j < NI; j++) {
            #pragma unroll
            for (int v = 0; v < 4; v++) {
                int rr = rb + i * 16 + g + (v >> 1) * 8;
                int cc = cb + j * 8 + q4 * 2 + (v & 1);
                int a = acc[i][j][v];
                if constexpr (MODE == 0) {
                    g_qkv[(long)rr * NCOL + cc] = a + g_biasi[cc];
                } else {
                    outf[(long)rr * NCOL + cc] = ((float)a * e1[cc]) * s5 + e2[cc];
                }
            }
        }
    }
}

// ---------------- launcher ----------------
extern "C" void kernel_launch(void* const* d_in, const int* in_sizes, int n_in,
                              void* d_out, int out_size) {
    const float* x0             = (const float*)d_in[0];
    const float* qkv_w          = (const float*)d_in[1];
    const float* qkv_b          = (const float*)d_in[2];
    const float* qkv_alpha      = (const float*)d_in[3];
    const float* qkv_act_alpha  = (const float*)d_in[4];
    const float* proj_w         = (const float*)d_in[5];
    const float* proj_b         = (const float*)d_in[6];
    const float* proj_alpha     = (const float*)d_in[7];
    const float* proj_act_alpha = (const float*)d_in[8];
    const float* norm_q_w       = (const float*)d_in[9];
    const float* norm_q_b       = (const float*)d_in[10];
    const float* norm_k_w       = (const float*)d_in[11];
    const float* norm_k_b       = (const float*)d_in[12];
    const float* q_alpha        = (const float*)d_in[13];
    const float* k_alpha        = (const float*)d_in[14];
    const float* v_alpha        = (const float*)d_in[15];
    const float* attn_alpha     = (const float*)d_in[16];
    float* out = (float*)d_out;

    cudaFuncSetAttribute(k_attn_fused, cudaFuncAttributeMaxDynamicSharedMemorySize, SMEM_FUSED);

    k_scalars<<<1, 256>>>(qkv_act_alpha, proj_act_alpha, q_alpha, k_alpha, v_alpha, attn_alpha);
    k_recips<<<(C3v + CH + 255) / 256, 256>>>(qkv_alpha, proj_alpha);
    k_quant_x0<<<(ROWS * CH + 255) / 256, 256>>>(x0);
    k_quant_wqkv<<<(C3v * CH + 255) / 256, 256>>>(qkv_w, qkv_alpha, qkv_b);
    k_quant_wproj<<<(CH * CH + 255) / 256, 256>>>(proj_w);

    // QKV GEMM: 4096 x 2304 x 768
    gemm_s8<0><<<dim3(C3v / 128, ROWS / 128, 1), 256>>>(nullptr, nullptr, nullptr);

    // per-row integer mean/var + quantization
    k_norm<<<dim3(SEQ / 128, 1, NBH), 128>>>(qkv_alpha, norm_q_w, norm_q_b, norm_k_w, norm_k_b);

    // fused QK -> exp2-softmax -> quantize -> PV
    k_attn_fused<<<dim3(SEQ / 128, NBH), 256, SMEM_FUSED>>>();

    // projection GEMM: 4096 x 768 x 768, fp32 epilogue to d_out
    gemm_s8<3><<<dim3(CH / 128, ROWS / 128, 1), 256>>>(out, proj_alpha, proj_b);
}

// round 5
// speedup vs baseline: 1.2067x; 1.0270x over previous
#include <cuda_runtime.h>
#include <stdint.h>

// ---------------- problem constants ----------------
constexpr int BATCH = 4, SEQ = 1024, CH = 768, HEADS = 12, HDIM = 64;
constexpr int ROWS = BATCH * SEQ;   // 4096
constexpr int C3v  = 3 * CH;        // 2304
constexpr int NBH  = BATCH * HEADS; // 48

// ---------------- scratch (__device__ globals; no runtime alloc) ----------------
__device__ __align__(256) int8_t g_x0q [ROWS * CH];
__device__ __align__(256) int8_t g_wqkv[C3v * CH];
__device__            int    g_biasi[C3v];
__device__ __align__(256) int8_t g_wproj[CH * CH];
__device__ __align__(256) float  g_rw  [C3v + CH];
__device__ __align__(256) int    g_qkv [ROWS * C3v];
__device__ __align__(256) int8_t g_q2  [NBH * SEQ * HDIM];
__device__ __align__(256) int8_t g_k2  [NBH * SEQ * HDIM];
__device__ __align__(256) int8_t g_v2t [NBH * HDIM * SEQ];
__device__ __align__(256) int8_t g_x1q [ROWS * CH];
// 0:a_in 1:aq 2:ak 3:av 4:am 5:ap 6:LOG2E*hs*aq*ak 7:am*av 8:1/a_in 9:(am*av)/ap
__device__            float  g_sc[12];

__device__ __forceinline__ float clip8(float x) { return fminf(fmaxf(x, -8.f), 7.f); }
__device__ __forceinline__ int8_t q8(float x) { return (int8_t)__float2int_rn(clip8(x)); }

// 2^floor(e)*(1+frac(e)) with e = acc * s6, computed as one FFMA + one F2I.
// bits = rn(acc*(s6*2^23) + 127*2^23); frac error <= 64/2^23.
__device__ __forceinline__ float pexp2i(int acc, float s6p) {
    return __int_as_float(__float2int_rn(fmaf((float)acc, s6p, 1065353216.0f)));
}

__device__ __forceinline__ void cp16(void* dst, const void* src) {
    uint32_t d = (uint32_t)__cvta_generic_to_shared(dst);
    asm volatile("cp.async.cg.shared.global [%0], [%1], 16;" :: "r"(d), "l"(src));
}
#define CP_COMMIT() asm volatile("cp.async.commit_group;")
#define CP_WAIT1()  asm volatile("cp.async.wait_group 1;")
#define CP_WAIT0()  asm volatile("cp.async.wait_group 0;")

__device__ __forceinline__ uint32_t smem_u32(const void* p) {
    return (uint32_t)__cvta_generic_to_shared(p);
}
__device__ __forceinline__ void ldsm4(uint32_t addr, uint32_t& r0, uint32_t& r1,
                                      uint32_t& r2, uint32_t& r3) {
    asm volatile("ldmatrix.sync.aligned.m8n8.x4.shared.b16 {%0,%1,%2,%3}, [%4];"
                 : "=r"(r0), "=r"(r1), "=r"(r2), "=r"(r3) : "r"(addr));
}

// ---------------- pre: scalar means + reciprocals ----------------
__global__ void k_pre(const float* __restrict__ qkv_act_alpha,
                      const float* __restrict__ proj_act_alpha,
                      const float* __restrict__ q_alpha,
                      const float* __restrict__ k_alpha,
                      const float* __restrict__ v_alpha,
                      const float* __restrict__ attn_alpha,
                      const float* __restrict__ qkv_alpha,
                      const float* __restrict__ proj_alpha) {
    __shared__ float sh[256];
    int t = threadIdx.x;
    for (int i = t; i < C3v + CH; i += 256)
        g_rw[i] = 1.0f / (i < C3v ? qkv_alpha[i] : proj_alpha[i - C3v]);
    float s = 0.f;
    for (int i = t; i < CH; i += 256) s += qkv_act_alpha[i];
    sh[t] = s; __syncthreads();
    for (int o = 128; o > 0; o >>= 1) { if (t < o) sh[t] += sh[t + o]; __syncthreads(); }
    float a_in = sh[0] / (float)CH;
    __syncthreads();
    s = 0.f;
    for (int i = t; i < CH; i += 256) s += proj_act_alpha[i];
    sh[t] = s; __syncthreads();
    for (int o = 128; o > 0; o >>= 1) { if (t < o) sh[t] += sh[t + o]; __syncthreads(); }
    float ap = sh[0] / (float)CH;
    if (t == 0) {
        float aq = 0.f, ak = 0.f, av = 0.f, am = 0.f;
        for (int i = 0; i < HEADS; i++) { aq += q_alpha[i]; ak += k_alpha[i]; av += v_alpha[i]; am += attn_alpha[i]; }
        aq /= HEADS; ak /= HEADS; av /= HEADS; am /= HEADS;
        g_sc[0] = a_in; g_sc[1] = aq; g_sc[2] = ak; g_sc[3] = av; g_sc[4] = am; g_sc[5] = ap;
        g_sc[6] = 1.4426950408889634f * ((0.125f * aq) * ak);
        g_sc[7] = am * av;
        g_sc[8] = 1.0f / a_in;
        g_sc[9] = (am * av) / ap;
    }
}

// ---------------- fused quantizer: x0, wqkv, wproj (4 int8 per store) ----------------
constexpr int NG_X0 = ROWS * CH / 4;      // 786432
constexpr int NG_WQ = C3v * CH / 4;       // 442368
constexpr int NG_WP = CH * CH / 4;        // 147456
constexpr int NG_ALL = NG_X0 + NG_WQ + NG_WP;

__device__ __forceinline__ uint32_t pack4(float a, float b, float c, float d) {
    return (uint32_t)(uint8_t)q8(a) | ((uint32_t)(uint8_t)q8(b) << 8) |
           ((uint32_t)(uint8_t)q8(c) << 16) | ((uint32_t)(uint8_t)q8(d) << 24);
}

__global__ void k_quant_all(const float* __restrict__ x0,
                            const float* __restrict__ qkv_w,
                            const float* __restrict__ proj_w) {
    int i = blockIdx.x * blockDim.x + threadIdx.x;
    if (i >= NG_ALL) return;
    if (i < NG_X0) {
        float r = g_sc[8];
        float4 v = ((const float4*)x0)[i];
        ((uint32_t*)g_x0q)[i] = pack4(v.x * r, v.y * r, v.z * r, v.w * r);
    } else if (i < NG_X0 + NG_WQ) {
        int k = i - NG_X0;
        float r = g_rw[k / (CH / 4)];
        float4 v = ((const float4*)qkv_w)[k];
        ((uint32_t*)g_wqkv)[k] = pack4(v.x * r, v.y * r, v.z * r, v.w * r);
    } else {
        int k = i - NG_X0 - NG_WQ;
        float r = g_rw[C3v + k / (CH / 4)];
        float4 v = ((const float4*)proj_w)[k];
        ((uint32_t*)g_wproj)[k] = pack4(v.x * r, v.y * r, v.z * r, v.w * r);
    }
}

__global__ void k_bias(const float* __restrict__ bvec, const float* __restrict__ alpha) {
    int o = blockIdx.x * blockDim.x + threadIdx.x;
    if (o < C3v) g_biasi[o] = (int)truncf(bvec[o] / g_sc[0] / alpha[o]);
}

// ---------------- int8 MMA GEMM (cp.async 2-stage + ldmatrix) ----------------
// MODE 0: qkv (A=g_x0q [4096x768], B=g_wqkv [2304x768], out g_qkv raw int32)
// MODE 1: proj (A=g_x1q, B=g_wproj, out fp32 scale+bias)
template <int MODE>
__global__ void __launch_bounds__(256) gemm_s8(float* __restrict__ outf,
                        const float* __restrict__ e1, const float* __restrict__ e2) {
    constexpr int K  = 768;
    constexpr int BM = 128, BN = 128, BK = 64;
    constexpr int NTHR = 256;
    constexpr int WM = 64, WN = 32;
    constexpr int MI = 4, NI = 4;
    constexpr int SAS = BK + 16;
    constexpr int NK = K / BK;  // 12

    __shared__ __align__(16) int8_t As[2][BM * SAS];
    __shared__ __align__(16) int8_t Bs[2][BN * SAS];

    const int8_t* A  = (MODE == 0) ? g_x0q  : g_x1q;
    const int8_t* Bw = (MODE == 0) ? g_wqkv : g_wproj;
    constexpr int NCOL = (MODE == 0) ? C3v : CH;

    int tid = threadIdx.x;
    int warp = tid >> 5, lane = tid & 31;
    int wr = warp / 4, wc = warp % 4;
    int g = lane >> 2, q4 = lane & 3;
    int rowBase = blockIdx.y * BM;
    int colBase = blockIdx.x * BN;

    // ldmatrix per-lane offsets
    uint32_t As_base = smem_u32(&As[0][0]);
    uint32_t Bs_base = smem_u32(&Bs[0][0]);
    uint32_t aoff = (uint32_t)(wr * WM + (lane & 15)) * SAS + ((lane >> 4) << 4);
    uint32_t boff = (uint32_t)(wc * WN + (lane & 7) + ((lane >> 4) << 3)) * SAS
                    + (((lane >> 3) & 1) << 4);

    auto load_stage = [&](int st, int k0) {
        #pragma unroll
        for (int idx = tid; idx < BM * BK / 16; idx += NTHR) {
            int r = idx / (BK / 16), seg = idx % (BK / 16);
            cp16(&As[st][r * SAS + seg * 16],
                 &A[(long)(rowBase + r) * K + k0 + seg * 16]);
        }
        #pragma unroll
        for (int idx = tid; idx < BN * BK / 16; idx += NTHR) {
            int r = idx / (BK / 16), seg = idx % (BK / 16);
            cp16(&Bs[st][r * SAS + seg * 16],
                 &Bw[(long)(colBase + r) * K + k0 + seg * 16]);
        }
    };

    int acc[MI][NI][4];
    #pragma unroll
    for (int i = 0; i < MI; i++)
        #pragma unroll
        for (int j = 0; j < NI; j++)
            #pragma unroll
            for (int v = 0; v < 4; v++) acc[i][j][v] = 0;

    load_stage(0, 0);
    CP_COMMIT();

    for (int it = 0; it < NK; it++) {
        int cur = it & 1;
        if (it + 1 < NK) {
            load_stage(cur ^ 1, (it + 1) * BK);
            CP_COMMIT();
            CP_WAIT1();
        } else {
            CP_WAIT0();
        }
        __syncthreads();

        uint32_t Abase = As_base + (uint32_t)cur * (BM * SAS) + aoff;
        uint32_t Bbase = Bs_base + (uint32_t)cur * (BN * SAS) + boff;

        #pragma unroll
        for (int ks = 0; ks < BK; ks += 32) {
            uint32_t bfr[2][4];
            #pragma unroll
            for (int jj = 0; jj < 2; jj++)
                ldsm4(Bbase + jj * (16 * SAS) + ks,
                      bfr[jj][0], bfr[jj][1], bfr[jj][2], bfr[jj][3]);
            #pragma unroll
            for (int i = 0; i < MI; i++) {
                uint32_t a0, a1, a2, a3;
                ldsm4(Abase + i * (16 * SAS) + ks, a0, a1, a2, a3);
                #pragma unroll
                for (int j = 0; j < NI; j++) {
                    uint32_t b0 = bfr[j >> 1][(j & 1) * 2];
                    uint32_t b1 = bfr[j >> 1][(j & 1) * 2 + 1];
                    asm volatile(
                        "mma.sync.aligned.m16n8k32.row.col.s32.s8.s8.s32 "
                        "{%0,%1,%2,%3},{%4,%5,%6,%7},{%8,%9},{%0,%1,%2,%3};"
                        : "+r"(acc[i][j][0]), "+r"(acc[i][j][1]),
                          "+r"(acc[i][j][2]), "+r"(acc[i][j][3])
                        : "r"(a0), "r"(a1), "r"(a2), "r"(a3),
                          "r"(b0), "r"(b1));
                }
            }
        }
        __syncthreads();
    }

    float s5 = g_sc[5];
    int rb = rowBase + wr * WM;
    int cb = colBase + wc * WN;
    #pragma unroll
    for (int i = 0; i < MI; i++) {
        #pragma unroll
        for (int j = 0; j < NI; j++) {
            #pragma unroll
            for (int v = 0; v < 4; v++) {
                int rr = rb + i * 16 + g + (v >> 1) * 8;
                int cc = cb + j * 8 + q4 * 2 + (v & 1);
                int a = acc[i][j][v];
                if constexpr (MODE == 0) {
                    g_qkv[(long)rr * NCOL + cc] = a;   // bias added in k_norm
                } else {
                    outf[(long)rr * NCOL + cc] = ((float)a * e1[cc]) * s5 + e2[cc];
                }
            }
        }
    }
}

// ---------------- integer mean/var norm + q/k/v quantization (bias folded in) ----------------
__global__ void __launch_bounds__(128) k_norm(
        const float* __restrict__ qkv_alpha,
        const float* __restrict__ nqw, const float* __restrict__ nqb,
        const float* __restrict__ nkw, const float* __restrict__ nkb) {
    int bh = blockIdx.z, b = bh / HEADS, h = bh % HEADS;
    int n0 = blockIdx.x * 128;
    int t = threadIdx.x;
    __shared__ int sm[128][65];
    __shared__ float alq[64], alk[64], alvs[64];
    __shared__ float boWq[64], woaq[64], boWk[64], woak[64];
    __shared__ int coef[64], biq[64], bik[64], biv[64];
    if (t < 64) {
        alq[t]  = qkv_alpha[h * HDIM + t];
        alk[t]  = qkv_alpha[CH + h * HDIM + t];
        alvs[t] = (g_sc[0] * qkv_alpha[2 * CH + h * HDIM + t]) / g_sc[3];
        float wq = nqw[t], wk = nkw[t];
        boWq[t] = nqb[t] / wq;  woaq[t] = wq / g_sc[1];
        boWk[t] = nkb[t] / wk;  woak[t] = wk / g_sc[2];
        coef[t] = 1024 / (t + 1);
        biq[t] = g_biasi[h * HDIM + t];
        bik[t] = g_biasi[CH + h * HDIM + t];
        biv[t] = g_biasi[2 * CH + h * HDIM + t];
    }
    __syncthreads();

    const long rowg = (long)(b * SEQ + n0);

    // ---- Q ----
    #pragma unroll 4
    for (int idx = t; idx < 128 * 64; idx += 128) {
        int r = idx >> 6, c = idx & 63;
        sm[r][c] = g_qkv[(rowg + r) * C3v + h * HDIM + c] + biq[c];
    }
    __syncthreads();
    {
        int m = 0, vv = 0;
        #pragma unroll 8
        for (int d = 0; d < HDIM; d++) {
            float xf = (float)sm[t][d] * alq[d];
            int xi = (int)xf;
            int dd = xi - m;
            m += (dd * coef[d]) >> 10;
            vv += dd * (xi - m);
        }
        float mu = (float)m;
        float invden = 1.0f / (sqrtf((float)vv * 0.015625f) + 1e-5f);
        int8_t* outq = g_q2 + ((long)bh * SEQ + n0 + t) * HDIM;
        #pragma unroll 8
        for (int d = 0; d < HDIM; d++) {
            float xf = (float)sm[t][d] * alq[d];
            float q1 = (xf - mu) * invden;
            outq[d] = q8((q1 + boWq[d]) * woaq[d]);
        }
    }
    __syncthreads();

    // ---- K ----
    #pragma unroll 4
    for (int idx = t; idx < 128 * 64; idx += 128) {
        int r = idx >> 6, c = idx & 63;
        sm[r][c] = g_qkv[(rowg + r) * C3v + CH + h * HDIM + c] + bik[c];
    }
    __syncthreads();
    {
        int m = 0, vv = 0;
        #pragma unroll 8
        for (int d = 0; d < HDIM; d++) {
            float xf = (float)sm[t][d] * alk[d];
            int xi = (int)xf;
            int dd = xi - m;
            m += (dd * coef[d]) >> 10;
            vv += dd * (xi - m);
        }
        float mu = (float)m;
        float invden = 1.0f / (sqrtf((float)vv * 0.015625f) + 1e-5f);
        int8_t* outk = g_k2 + ((long)bh * SEQ + n0 + t) * HDIM;
        #pragma unroll 8
        for (int d = 0; d < HDIM; d++) {
            float xf = (float)sm[t][d] * alk[d];
            float k1 = (xf - mu) * invden;
            outk[d] = q8((k1 + boWk[d]) * woak[d]);
        }
    }
    __syncthreads();

    // ---- V (transposed write) ----
    #pragma unroll 4
    for (int idx = t; idx < 128 * 64; idx += 128) {
        int r = idx >> 6, c = idx & 63;
        sm[r][c] = g_qkv[(rowg + r) * C3v + 2 * CH + h * HDIM + c] + biv[c];
    }
    __syncthreads();
    {
        int8_t* outv = g_v2t + (long)bh * HDIM * SEQ + n0 + t;
        #pragma unroll 8
        for (int d = 0; d < HDIM; d++)
            outv[d * SEQ] = q8((float)sm[t][d] * alvs[d]);
    }
}

// ---------------- fused flash-style attention ----------------
constexpr int OFF_K = 0;
constexpr int OFF_V = 81920;
constexpr int OFF_Q = 148480;
constexpr int OFF_A = 158720;
constexpr int OFF_S = 177152;
constexpr int SMEM_FUSED = 177664;

__global__ void __launch_bounds__(256, 1) k_attn_fused() {
    extern __shared__ __align__(16) int8_t sh[];
    int8_t* Ksm = sh + OFF_K;
    int8_t* Vsm = sh + OFF_V;
    int8_t* Qsm = sh + OFF_Q;
    int8_t* Asm = sh + OFF_A;
    float*  rs  = (float*)(sh + OFF_S);

    int bh = blockIdx.y, b = bh / HEADS, h = bh % HEADS;
    int qBase = blockIdx.x * 128;
    int tid = threadIdx.x, warp = tid >> 5, lane = tid & 31;
    int g = lane >> 2, q4 = lane & 3;
    int wr = warp >> 2, wc = warp & 3;

    const int8_t* Qg = g_q2 + ((long)bh * SEQ + qBase) * HDIM;
    const int8_t* Kg = g_k2 + (long)bh * SEQ * HDIM;
    const int8_t* Vg = g_v2t + (long)bh * HDIM * SEQ;

    for (int idx = tid; idx < 512; idx += 256) {
        int r = idx >> 2, s = idx & 3;
        cp16(&Qsm[r * 80 + s * 16], &Qg[r * 64 + s * 16]);
    }
    for (int idx = tid; idx < 4096; idx += 256) {
        int r = idx >> 2, s = idx & 3;
        cp16(&Ksm[r * 80 + s * 16], &Kg[r * 64 + s * 16]);
    }
    for (int idx = tid; idx < 4096; idx += 256) {
        int r = idx >> 6, s = idx & 63;
        cp16(&Vsm[r * 1040 + s * 16], &Vg[r * 1024 + s * 16]);
    }
    CP_COMMIT();
    if (tid < 128) rs[tid] = 0.f;
    CP_WAIT0();
    __syncthreads();

    float s6p = g_sc[6] * 8388608.0f;

    // pass 1: row sums of exp2 numerator
    for (int c = 0; c < 8; c++) {
        int acc[4][4][4] = {};
        #pragma unroll
        for (int ks = 0; ks < 64; ks += 32) {
            uint32_t bf[4][2];
            #pragma unroll
            for (int j = 0; j < 4; j++) {
                const int8_t* bp = &Ksm[(c * 128 + wc * 32 + j * 8 + g) * 80 + ks + q4 * 4];
                bf[j][0] = *(const uint32_t*)bp;
                bf[j][1] = *(const uint32_t*)(bp + 16);
            }
            #pragma unroll
            for (int i = 0; i < 4; i++) {
                const int8_t* ap0 = &Qsm[(wr * 64 + i * 16 + g) * 80 + ks + q4 * 4];
                uint32_t a0 = *(const uint32_t*)ap0;
                uint32_t a2 = *(const uint32_t*)(ap0 + 16);
                const int8_t* ap1 = ap0 + 8 * 80;
                uint32_t a1 = *(const uint32_t*)ap1;
                uint32_t a3 = *(const uint32_t*)(ap1 + 16);
                #pragma unroll
                for (int j = 0; j < 4; j++) {
                    asm volatile(
                        "mma.sync.aligned.m16n8k32.row.col.s32.s8.s8.s32 "
                        "{%0,%1,%2,%3},{%4,%5,%6,%7},{%8,%9},{%0,%1,%2,%3};"
                        : "+r"(acc[i][j][0]), "+r"(acc[i][j][1]),
                          "+r"(acc[i][j][2]), "+r"(acc[i][j][3])
                        : "r"(a0), "r"(a1), "r"(a2), "r"(a3),
                          "r"(bf[j][0]), "r"(bf[j][1]));
                }
            }
        }
        #pragma unroll
        for (int i = 0; i < 4; i++) {
            #pragma unroll
            for (int part = 0; part < 2; part++) {
                float p = 0.f;
                #pragma unroll
                for (int j = 0; j < 4; j++) {
                    #pragma unroll
                    for (int vp = 0; vp < 2; vp++)
                        p += pexp2i(acc[i][j][part * 2 + vp], s6p);
                }
                p += __shfl_xor_sync(0xffffffffu, p, 1);
                p += __shfl_xor_sync(0xffffffffu, p, 2);
                if (q4 == 0) atomicAdd(&rs[wr * 64 + i * 16 + g + part * 8], p);
            }
        }
    }
    __syncthreads();
    if (tid < 128) rs[tid] = 1.0f / (rs[tid] * g_sc[4]);
    __syncthreads();

    // pass 2: recompute, quantize attn, PV
    int pv[4][2][4] = {};
    for (int c = 0; c < 8; c++) {
        int acc[4][4][4] = {};
        #pragma unroll
        for (int ks = 0; ks < 64; ks += 32) {
            uint32_t bf[4][2];
            #pragma unroll
            for (int j = 0; j < 4; j++) {
                const int8_t* bp = &Ksm[(c * 128 + wc * 32 + j * 8 + g) * 80 + ks + q4 * 4];
                bf[j][0] = *(const uint32_t*)bp;
                bf[j][1] = *(const uint32_t*)(bp + 16);
            }
            #pragma unroll
            for (int i = 0; i < 4; i++) {
                const int8_t* ap0 = &Qsm[(wr * 64 + i * 16 + g) * 80 + ks + q4 * 4];
                uint32_t a0 = *(const uint32_t*)ap0;
                uint32_t a2 = *(const uint32_t*)(ap0 + 16);
                const int8_t* ap1 = ap0 + 8 * 80;
                uint32_t a1 = *(const uint32_t*)ap1;
                uint32_t a3 = *(const uint32_t*)(ap1 + 16);
                #pragma unroll
                for (int j = 0; j < 4; j++) {
                    asm volatile(
                        "mma.sync.aligned.m16n8k32.row.col.s32.s8.s8.s32 "
                        "{%0,%1,%2,%3},{%4,%5,%6,%7},{%8,%9},{%0,%1,%2,%3};"
                        : "+r"(acc[i][j][0]), "+r"(acc[i][j][1]),
                          "+r"(acc[i][j][2]), "+r"(acc[i][j][3])
                        : "r"(a0), "r"(a1), "r"(a2), "r"(a3),
                          "r"(bf[j][0]), "r"(bf[j][1]));
                }
            }
        }
        #pragma unroll
        for (int i = 0; i < 4; i++) {
            #pragma unroll
            for (int part = 0; part < 2; part++) {
                int row = wr * 64 + i * 16 + g + part * 8;
                float iv = rs[row];
                #pragma unroll
                for (int j = 0; j < 4; j++) {
                    float p0 = pexp2i(acc[i][j][part * 2 + 0], s6p);
                    float p1 = pexp2i(acc[i][j][part * 2 + 1], s6p);
                    uint8_t v0 = (uint8_t)q8(p0 * iv);
                    uint8_t v1 = (uint8_t)q8(p1 * iv);
                    uint16_t pk = (uint16_t)v0 | ((uint16_t)v1 << 8);
                    *(uint16_t*)&Asm[row * 144 + wc * 32 + j * 8 + q4 * 2] = pk;
                }
            }
        }
        __syncthreads();
        #pragma unroll
        for (int ks = 0; ks < 128; ks += 32) {
            uint32_t bf[2][2];
            #pragma unroll
            for (int j = 0; j < 2; j++) {
                const int8_t* bp = &Vsm[(wc * 16 + j * 8 + g) * 1040 + c * 128 + ks + q4 * 4];
                bf[j][0] = *(const uint32_t*)bp;
                bf[j][1] = *(const uint32_t*)(bp + 16);
            }
            #pragma unroll
            for (int i = 0; i < 4; i++) {
                const int8_t* ap0 = &Asm[(wr * 64 + i * 16 + g) * 144 + ks + q4 * 4];
                uint32_t a0 = *(const uint32_t*)ap0;
                uint32_t a2 = *(const uint32_t*)(ap0 + 16);
                const int8_t* ap1 = ap0 + 8 * 144;
                uint32_t a1 = *(const uint32_t*)ap1;
                uint32_t a3 = *(const uint32_t*)(ap1 + 16);
                #pragma unroll
                for (int j = 0; j < 2; j++) {
                    asm volatile(
                        "mma.sync.aligned.m16n8k32.row.col.s32.s8.s8.s32 "
                        "{%0,%1,%2,%3},{%4,%5,%6,%7},{%8,%9},{%0,%1,%2,%3};"
                        : "+r"(pv[i][j][0]), "+r"(pv[i][j][1]),
                          "+r"(pv[i][j][2]), "+r"(pv[i][j][3])
                        : "r"(a0), "r"(a1), "r"(a2), "r"(a3),
                          "r"(bf[j][0]), "r"(bf[j][1]));
                }
            }
        }
        __syncthreads();
    }

    float r9 = g_sc[9];
    #pragma unroll
    for (int i = 0; i < 4; i++) {
        #pragma unroll
        for (int j = 0; j < 2; j++) {
            #pragma unroll
            for (int v = 0; v < 4; v++) {
                int rr = qBase + wr * 64 + i * 16 + g + (v >> 1) * 8;
                int cc = wc * 16 + j * 8 + q4 * 2 + (v & 1);
                float x = (float)pv[i][j][v] * r9;
                g_x1q[((long)(b * SEQ + rr)) * CH + h * HDIM + cc] = q8(x);
            }
        }
    }
}

// ---------------- launcher ----------------
extern "C" void kernel_launch(void* const* d_in, const int* in_sizes, int n_in,
                              void* d_out, int out_size) {
    const float* x0             = (const float*)d_in[0];
    const float* qkv_w          = (const float*)d_in[1];
    const float* qkv_b          = (const float*)d_in[2];
    const float* qkv_alpha      = (const float*)d_in[3];
    const float* qkv_act_alpha  = (const float*)d_in[4];
    const float* proj_w         = (const float*)d_in[5];
    const float* proj_b         = (const float*)d_in[6];
    const float* proj_alpha     = (const float*)d_in[7];
    const float* proj_act_alpha = (const float*)d_in[8];
    const float* norm_q_w       = (const float*)d_in[9];
    const float* norm_q_b       = (const float*)d_in[10];
    const float* norm_k_w       = (const float*)d_in[11];
    const float* norm_k_b       = (const float*)d_in[12];
    const float* q_alpha        = (const float*)d_in[13];
    const float* k_alpha        = (const float*)d_in[14];
    const float* v_alpha        = (const float*)d_in[15];
    const float* attn_alpha     = (const float*)d_in[16];
    float* out = (float*)d_out;

    cudaFuncSetAttribute(k_attn_fused, cudaFuncAttributeMaxDynamicSharedMemorySize, SMEM_FUSED);

    // launch 1
    k_pre<<<1, 256>>>(qkv_act_alpha, proj_act_alpha, q_alpha, k_alpha, v_alpha,
                      attn_alpha, qkv_alpha, proj_alpha);
    // launch 2
    k_quant_all<<<(NG_ALL + 255) / 256, 256>>>(x0, qkv_w, proj_w);
    // launch 3
    k_bias<<<(C3v + 255) / 256, 256>>>(qkv_b, qkv_alpha);
    // launch 4 (ncu capture target): QKV GEMM 4096 x 2304 x 768
    gemm_s8<0><<<dim3(C3v / 128, ROWS / 128, 1), 256>>>(nullptr, nullptr, nullptr);
    // launch 5
    k_norm<<<dim3(SEQ / 128, 1, NBH), 128>>>(qkv_alpha, norm_q_w, norm_q_b, norm_k_w, norm_k_b);
    // launch 6: fused QK -> exp2-softmax -> quantize -> PV
    k_attn_fused<<<dim3(SEQ / 128, NBH), 256, SMEM_FUSED>>>();
    // launch 7: projection GEMM 4096 x 768 x 768
    gemm_s8<1><<<dim3(CH / 128, ROWS / 128, 1), 256>>>(out, proj_alpha, proj_b);
}

// round 6
// speedup vs baseline: 1.4389x; 1.1924x over previous
#include <cuda_runtime.h>
#include <stdint.h>

// ---------------- problem constants ----------------
constexpr int BATCH = 4, SEQ = 1024, CH = 768, HEADS = 12, HDIM = 64;
constexpr int ROWS = BATCH * SEQ;   // 4096
constexpr int C3v  = 3 * CH;        // 2304
constexpr int NBH  = BATCH * HEADS; // 48

// ---------------- scratch ----------------
__device__ __align__(256) int8_t g_x0q [ROWS * CH];
__device__ __align__(256) int8_t g_wqkv[C3v * CH];
__device__            int    g_biasi[C3v];
__device__ __align__(256) int8_t g_wproj[CH * CH];
__device__ __align__(256) float  g_rw  [C3v + CH];
__device__ __align__(256) int8_t g_q2  [NBH * SEQ * HDIM];
__device__ __align__(256) int8_t g_k2  [NBH * SEQ * HDIM];
__device__ __align__(256) int8_t g_v2t [NBH * HDIM * SEQ];
__device__ __align__(256) int8_t g_x1q [ROWS * CH];
// 0:a_in 1:aq 2:ak 3:av 4:am 5:ap 6:LOG2E*hs*aq*ak 7:am*av 8:1/a_in 9:(am*av)/ap
__device__            float  g_sc[12];

__device__ __forceinline__ float clip8(float x) { return fminf(fmaxf(x, -8.f), 7.f); }
__device__ __forceinline__ int8_t q8(float x) { return (int8_t)__float2int_rn(clip8(x)); }

// 2^floor(e)*(1+frac(e)), e = acc*s6: one FFMA + one F2I (bits = rn(acc*s6*2^23 + 127*2^23))
__device__ __forceinline__ float pexp2i(int acc, float s6p) {
    return __int_as_float(__float2int_rn(fmaf((float)acc, s6p, 1065353216.0f)));
}

__device__ __forceinline__ void cp16(void* dst, const void* src) {
    uint32_t d = (uint32_t)__cvta_generic_to_shared(dst);
    asm volatile("cp.async.cg.shared.global [%0], [%1], 16;" :: "r"(d), "l"(src));
}
#define CP_COMMIT() asm volatile("cp.async.commit_group;")
#define CP_WAIT1()  asm volatile("cp.async.wait_group 1;")
#define CP_WAIT0()  asm volatile("cp.async.wait_group 0;")

__device__ __forceinline__ uint32_t smem_u32(const void* p) {
    return (uint32_t)__cvta_generic_to_shared(p);
}
__device__ __forceinline__ void ldsm4(uint32_t addr, uint32_t& r0, uint32_t& r1,
                                      uint32_t& r2, uint32_t& r3) {
    asm volatile("ldmatrix.sync.aligned.m8n8.x4.shared.b16 {%0,%1,%2,%3}, [%4];"
                 : "=r"(r0), "=r"(r1), "=r"(r2), "=r"(r3) : "r"(addr));
}
#define MMA_S8(acc, a0, a1, a2, a3, b0, b1) \
    asm volatile("mma.sync.aligned.m16n8k32.row.col.s32.s8.s8.s32 " \
                 "{%0,%1,%2,%3},{%4,%5,%6,%7},{%8,%9},{%0,%1,%2,%3};" \
                 : "+r"((acc)[0]), "+r"((acc)[1]), "+r"((acc)[2]), "+r"((acc)[3]) \
                 : "r"(a0), "r"(a1), "r"(a2), "r"(a3), "r"(b0), "r"(b1))

// ---------------- pre: scalar means + reciprocals + integer bias ----------------
__global__ void k_pre(const float* __restrict__ qkv_act_alpha,
                      const float* __restrict__ proj_act_alpha,
                      const float* __restrict__ q_alpha,
                      const float* __restrict__ k_alpha,
                      const float* __restrict__ v_alpha,
                      const float* __restrict__ attn_alpha,
                      const float* __restrict__ qkv_alpha,
                      const float* __restrict__ proj_alpha,
                      const float* __restrict__ qkv_b) {
    __shared__ float sh[256];
    int t = threadIdx.x;
    for (int i = t; i < C3v + CH; i += 256)
        g_rw[i] = 1.0f / (i < C3v ? qkv_alpha[i] : proj_alpha[i - C3v]);
    float s = 0.f;
    for (int i = t; i < CH; i += 256) s += qkv_act_alpha[i];
    sh[t] = s; __syncthreads();
    for (int o = 128; o > 0; o >>= 1) { if (t < o) sh[t] += sh[t + o]; __syncthreads(); }
    float a_in = sh[0] / (float)CH;
    __syncthreads();
    // integer bias (needs a_in)
    for (int o = t; o < C3v; o += 256)
        g_biasi[o] = (int)truncf(qkv_b[o] / a_in / qkv_alpha[o]);
    s = 0.f;
    for (int i = t; i < CH; i += 256) s += proj_act_alpha[i];
    sh[t] = s; __syncthreads();
    for (int o = 128; o > 0; o >>= 1) { if (t < o) sh[t] += sh[t + o]; __syncthreads(); }
    float ap = sh[0] / (float)CH;
    if (t == 0) {
        float aq = 0.f, ak = 0.f, av = 0.f, am = 0.f;
        for (int i = 0; i < HEADS; i++) { aq += q_alpha[i]; ak += k_alpha[i]; av += v_alpha[i]; am += attn_alpha[i]; }
        aq /= HEADS; ak /= HEADS; av /= HEADS; am /= HEADS;
        g_sc[0] = a_in; g_sc[1] = aq; g_sc[2] = ak; g_sc[3] = av; g_sc[4] = am; g_sc[5] = ap;
        g_sc[6] = 1.4426950408889634f * ((0.125f * aq) * ak);
        g_sc[7] = am * av;
        g_sc[8] = 1.0f / a_in;
        g_sc[9] = (am * av) / ap;
    }
}

// ---------------- fused quantizer ----------------
constexpr int NG_X0 = ROWS * CH / 4;
constexpr int NG_WQ = C3v * CH / 4;
constexpr int NG_WP = CH * CH / 4;
constexpr int NG_ALL = NG_X0 + NG_WQ + NG_WP;

__device__ __forceinline__ uint32_t pack4(float a, float b, float c, float d) {
    return (uint32_t)(uint8_t)q8(a) | ((uint32_t)(uint8_t)q8(b) << 8) |
           ((uint32_t)(uint8_t)q8(c) << 16) | ((uint32_t)(uint8_t)q8(d) << 24);
}

__global__ void k_quant_all(const float* __restrict__ x0,
                            const float* __restrict__ qkv_w,
                            const float* __restrict__ proj_w) {
    int i = blockIdx.x * blockDim.x + threadIdx.x;
    if (i >= NG_ALL) return;
    if (i < NG_X0) {
        float r = g_sc[8];
        float4 v = ((const float4*)x0)[i];
        ((uint32_t*)g_x0q)[i] = pack4(v.x * r, v.y * r, v.z * r, v.w * r);
    } else if (i < NG_X0 + NG_WQ) {
        int k = i - NG_X0;
        float r = g_rw[k / (CH / 4)];
        float4 v = ((const float4*)qkv_w)[k];
        ((uint32_t*)g_wqkv)[k] = pack4(v.x * r, v.y * r, v.z * r, v.w * r);
    } else {
        int k = i - NG_X0 - NG_WQ;
        float r = g_rw[C3v + k / (CH / 4)];
        float4 v = ((const float4*)proj_w)[k];
        ((uint32_t*)g_wproj)[k] = pack4(v.x * r, v.y * r, v.z * r, v.w * r);
    }
}

// ---------------- int8 MMA GEMM, 3-stage cp.async, fused norm epilogue (MODE 0) ----------------
// MODE 0: qkv (A=g_x0q, B=g_wqkv) -> norm in epilogue -> g_q2/g_k2/g_v2t
// MODE 1: proj (A=g_x1q, B=g_wproj) -> d_out fp32
constexpr int GSM = 128 * 130 * 4;  // 66560: epilogue int tile; >= 6*128*80 pipeline
template <int MODE>
__global__ void __launch_bounds__(256) gemm_s8(float* __restrict__ outf,
        const float* __restrict__ qkv_alpha,
        const float* __restrict__ nqw, const float* __restrict__ nqb,
        const float* __restrict__ nkw, const float* __restrict__ nkb,
        const float* __restrict__ e1, const float* __restrict__ e2) {
    constexpr int K  = 768;
    constexpr int BM = 128, BN = 128, BK = 64;
    constexpr int NTHR = 256;
    constexpr int WM = 64, WN = 32;
    constexpr int MI = 4, NI = 4;
    constexpr int SAS = BK + 16;
    constexpr int NK = K / BK;  // 12

    extern __shared__ __align__(16) int8_t dsm[];
    int8_t* As = dsm;                        // 3 * BM*SAS
    int8_t* Bs = dsm + 3 * BM * SAS;

    const int8_t* A  = (MODE == 0) ? g_x0q  : g_x1q;
    const int8_t* Bw = (MODE == 0) ? g_wqkv : g_wproj;

    int tid = threadIdx.x;
    int warp = tid >> 5, lane = tid & 31;
    int wr = warp / 4, wc = warp % 4;
    int g = lane >> 2, q4 = lane & 3;
    int rowBase = blockIdx.y * BM;
    int colBase = blockIdx.x * BN;

    uint32_t As_base = smem_u32(As);
    uint32_t Bs_base = smem_u32(Bs);
    uint32_t aoff = (uint32_t)(wr * WM + (lane & 15)) * SAS + ((lane >> 4) << 4);
    uint32_t boff = (uint32_t)(wc * WN + (lane & 7) + ((lane >> 4) << 3)) * SAS
                    + (((lane >> 3) & 1) << 4);

    auto load_stage = [&](int st, int k0) {
        #pragma unroll
        for (int idx = tid; idx < BM * BK / 16; idx += NTHR) {
            int r = idx / (BK / 16), seg = idx % (BK / 16);
            cp16(&As[st * BM * SAS + r * SAS + seg * 16],
                 &A[(long)(rowBase + r) * K + k0 + seg * 16]);
        }
        #pragma unroll
        for (int idx = tid; idx < BN * BK / 16; idx += NTHR) {
            int r = idx / (BK / 16), seg = idx % (BK / 16);
            cp16(&Bs[st * BN * SAS + r * SAS + seg * 16],
                 &Bw[(long)(colBase + r) * K + k0 + seg * 16]);
        }
    };

    int acc[MI][NI][4];
    #pragma unroll
    for (int i = 0; i < MI; i++)
        #pragma unroll
        for (int j = 0; j < NI; j++)
            #pragma unroll
            for (int v = 0; v < 4; v++) acc[i][j][v] = 0;

    load_stage(0, 0); CP_COMMIT();
    load_stage(1, BK); CP_COMMIT();

    for (int it = 0; it < NK; it++) {
        if (it < NK - 1) { CP_WAIT1(); } else { CP_WAIT0(); }
        __syncthreads();
        if (it + 2 < NK) { load_stage((it + 2) % 3, (it + 2) * BK); CP_COMMIT(); }

        int slot = it % 3;
        uint32_t Abase = As_base + (uint32_t)slot * (BM * SAS) + aoff;
        uint32_t Bbase = Bs_base + (uint32_t)slot * (BN * SAS) + boff;

        #pragma unroll
        for (int ks = 0; ks < BK; ks += 32) {
            uint32_t bfr[2][4];
            #pragma unroll
            for (int jj = 0; jj < 2; jj++)
                ldsm4(Bbase + jj * (16 * SAS) + ks,
                      bfr[jj][0], bfr[jj][1], bfr[jj][2], bfr[jj][3]);
            #pragma unroll
            for (int i = 0; i < MI; i++) {
                uint32_t a0, a1, a2, a3;
                ldsm4(Abase + i * (16 * SAS) + ks, a0, a1, a2, a3);
                #pragma unroll
                for (int j = 0; j < NI; j++)
                    MMA_S8(acc[i][j], a0, a1, a2, a3,
                           bfr[j >> 1][(j & 1) * 2], bfr[j >> 1][(j & 1) * 2 + 1]);
            }
        }
    }
    __syncthreads();   // all compute done before smem reuse / epilogue

    if constexpr (MODE == 1) {
        float s5 = g_sc[5];
        int rb = rowBase + wr * WM;
        int cb = colBase + wc * WN;
        #pragma unroll
        for (int i = 0; i < MI; i++)
            #pragma unroll
            for (int j = 0; j < NI; j++)
                #pragma unroll
                for (int v = 0; v < 4; v++) {
                    int rr = rb + i * 16 + g + (v >> 1) * 8;
                    int cc = cb + j * 8 + q4 * 2 + (v & 1);
                    outf[(long)rr * CH + cc] = ((float)acc[i][j][v] * e1[cc]) * s5 + e2[cc];
                }
    } else {
        // ---- fused integer mean/var norm + q/k/v quantization ----
        __shared__ float sA[130], sP1[130], sP2[130];
        __shared__ int   sBi[130], coef[64];
        int* sm32 = (int*)dsm;   // 128 rows x stride 130 words

        // params: local col t -> d = t&63, hs = t>>6; interleaved idx = d*2+hs
        if (tid < 128) {
            int col = colBase + tid;
            int d = tid & 63, hs = tid >> 6;
            int idx = d * 2 + hs;
            int branch = col / CH;
            sBi[idx] = g_biasi[col];
            if (branch == 0) {
                float w = nqw[d];
                sA[idx]  = qkv_alpha[col];
                sP1[idx] = nqb[d] / w;
                sP2[idx] = w / g_sc[1];
            } else if (branch == 1) {
                float w = nkw[d];
                sA[idx]  = qkv_alpha[col];
                sP1[idx] = nkb[d] / w;
                sP2[idx] = w / g_sc[2];
            } else {
                sA[idx]  = (g_sc[0] * qkv_alpha[col]) / g_sc[3];
                sP1[idx] = 0.f; sP2[idx] = 0.f;
            }
        }
        if (tid < 64) coef[tid] = 1024 / (tid + 1);

        // stage acc tile into smem (padded: cc -> cc + (cc>>6))
        int rbL = wr * WM, cbL = wc * WN;
        #pragma unroll
        for (int i = 0; i < MI; i++)
            #pragma unroll
            for (int j = 0; j < NI; j++)
                #pragma unroll
                for (int v = 0; v < 4; v++) {
                    int rr = rbL + i * 16 + g + (v >> 1) * 8;
                    int cc = cbL + j * 8 + q4 * 2 + (v & 1);
                    sm32[rr * 130 + cc + (cc >> 6)] = acc[i][j][v];
                }
        __syncthreads();

        // scan: thread t -> row r = t>>1, head-slice hs = t&1
        int r = tid >> 1, hs = tid & 1;
        int slice = (colBase >> 6) + hs;
        int branch = slice / HEADS;       // uniform per CTA
        int hh = slice % HEADS;
        int rrG = rowBase + r;
        int bb = rrG >> 10, nn = rrG & 1023;
        int bhh = bb * HEADS + hh;
        const int base = r * 130 + hs * 65;

        if (branch < 2) {
            int m = 0, vv = 0;
            #pragma unroll 8
            for (int d = 0; d < HDIM; d++) {
                int ival = sm32[base + d] + sBi[d * 2 + hs];
                float xf = (float)ival * sA[d * 2 + hs];
                int xi = (int)xf;
                int dd = xi - m;
                m += (dd * coef[d]) >> 10;
                vv += dd * (xi - m);
            }
            float mu = (float)m;
            float invden = 1.0f / (sqrtf((float)vv * 0.015625f) + 1e-5f);
            uint32_t* outp = (uint32_t*)((branch == 0 ? g_q2 : g_k2)
                              + ((long)bhh * SEQ + nn) * HDIM);
            #pragma unroll 4
            for (int dw = 0; dw < 16; dw++) {
                uint32_t pk = 0;
                #pragma unroll
                for (int kk = 0; kk < 4; kk++) {
                    int d = dw * 4 + kk;
                    int ival = sm32[base + d] + sBi[d * 2 + hs];
                    float xf = (float)ival * sA[d * 2 + hs];
                    float q1 = (xf - mu) * invden;
                    pk |= ((uint32_t)(uint8_t)q8((q1 + sP1[d * 2 + hs]) * sP2[d * 2 + hs]))
                          << (kk * 8);
                }
                outp[dw] = pk;
            }
        } else {
            int8_t* outv = g_v2t + (long)bhh * HDIM * SEQ + nn;
            #pragma unroll 8
            for (int d = 0; d < HDIM; d++) {
                int ival = sm32[base + d] + sBi[d * 2 + hs];
                outv[d * SEQ] = q8((float)ival * sA[d * 2 + hs]);
            }
        }
    }
}

// ---------------- single-pass fused flash attention ----------------
// grid (SEQ/32, NBH), 256 threads (8 warps). Q tile = 32 rows; all 32x1024 QK
// scores live in registers (128/thread); one QK pass, then PV.
constexpr int OFF_K = 0;                        // 1024 x 64, stride 80 -> 81920
constexpr int OFF_V = 81920;                    // 64 x 1024, stride 1040 -> 66560
constexpr int OFF_Q = 148480;                   // 32 x 64, stride 80 -> 2560
constexpr int OFF_A = 151040;                   // 32 x 1024 int8, stride 1040 -> 33280
constexpr int OFF_S = 184320;                   // 32 floats
constexpr int SMEM_FUSED = 184448;

__global__ void __launch_bounds__(256, 1) k_attn_fused() {
    extern __shared__ __align__(16) int8_t sh[];
    int8_t* Ksm = sh + OFF_K;
    int8_t* Vsm = sh + OFF_V;
    int8_t* Qsm = sh + OFF_Q;
    int8_t* Asm = sh + OFF_A;
    float*  rs  = (float*)(sh + OFF_S);

    int bh = blockIdx.y, b = bh / HEADS, h = bh % HEADS;
    int qBase = blockIdx.x * 32;
    int tid = threadIdx.x, w = tid >> 5, lane = tid & 31;
    int g = lane >> 2, q4 = lane & 3;

    const int8_t* Qg = g_q2 + ((long)bh * SEQ + qBase) * HDIM;
    const int8_t* Kg = g_k2 + (long)bh * SEQ * HDIM;
    const int8_t* Vg = g_v2t + (long)bh * HDIM * SEQ;

    if (tid < 128) {
        int r = tid >> 2, s = tid & 3;
        cp16(&Qsm[r * 80 + s * 16], &Qg[r * 64 + s * 16]);
    }
    for (int idx = tid; idx < 4096; idx += 256) {
        int r = idx >> 2, s = idx & 3;
        cp16(&Ksm[r * 80 + s * 16], &Kg[r * 64 + s * 16]);
    }
    for (int idx = tid; idx < 4096; idx += 256) {
        int r = idx >> 6, s = idx & 63;
        cp16(&Vsm[r * 1040 + s * 16], &Vg[r * 1024 + s * 16]);
    }
    CP_COMMIT();
    if (tid < 32) rs[tid] = 0.f;
    CP_WAIT0();
    __syncthreads();

    float s6p = g_sc[6] * 8388608.0f;

    // ---- QK: warp w computes cols [w*128, w*128+128) for all 32 rows ----
    int acc[2][16][4];
    #pragma unroll
    for (int i = 0; i < 2; i++)
        #pragma unroll
        for (int j = 0; j < 16; j++)
            #pragma unroll
            for (int v = 0; v < 4; v++) acc[i][j][v] = 0;

    #pragma unroll
    for (int ks = 0; ks < 64; ks += 32) {
        uint32_t a[2][4];
        #pragma unroll
        for (int i = 0; i < 2; i++) {
            const int8_t* ap0 = &Qsm[(i * 16 + g) * 80 + ks + q4 * 4];
            a[i][0] = *(const uint32_t*)ap0;
            a[i][2] = *(const uint32_t*)(ap0 + 16);
            const int8_t* ap1 = ap0 + 8 * 80;
            a[i][1] = *(const uint32_t*)ap1;
            a[i][3] = *(const uint32_t*)(ap1 + 16);
        }
        #pragma unroll
        for (int j = 0; j < 16; j++) {
            const int8_t* bp = &Ksm[(w * 128 + j * 8 + g) * 80 + ks + q4 * 4];
            uint32_t b0 = *(const uint32_t*)bp;
            uint32_t b1 = *(const uint32_t*)(bp + 16);
            MMA_S8(acc[0][j], a[0][0], a[0][1], a[0][2], a[0][3], b0, b1);
            MMA_S8(acc[1][j], a[1][0], a[1][1], a[1][2], a[1][3], b0, b1);
        }
    }

    // ---- row sums of exp2 numerator ----
    #pragma unroll
    for (int i = 0; i < 2; i++) {
        #pragma unroll
        for (int part = 0; part < 2; part++) {
            float p = 0.f;
            #pragma unroll
            for (int j = 0; j < 16; j++)
                p += pexp2i(acc[i][j][part * 2 + 0], s6p)
                   + pexp2i(acc[i][j][part * 2 + 1], s6p);
            p += __shfl_xor_sync(0xffffffffu, p, 1);
            p += __shfl_xor_sync(0xffffffffu, p, 2);
            if (q4 == 0) atomicAdd(&rs[i * 16 + g + part * 8], p);
        }
    }
    __syncthreads();
    if (tid < 32) rs[tid] = 1.0f / (rs[tid] * g_sc[4]);
    __syncthreads();

    // ---- quantize attn into smem ----
    #pragma unroll
    for (int i = 0; i < 2; i++) {
        #pragma unroll
        for (int part = 0; part < 2; part++) {
            int row = i * 16 + g + part * 8;
            float iv = rs[row];
            #pragma unroll
            for (int j = 0; j < 16; j++) {
                uint8_t v0 = (uint8_t)q8(pexp2i(acc[i][j][part * 2 + 0], s6p) * iv);
                uint8_t v1 = (uint8_t)q8(pexp2i(acc[i][j][part * 2 + 1], s6p) * iv);
                *(uint16_t*)&Asm[row * 1040 + w * 128 + j * 8 + q4 * 2] =
                    (uint16_t)v0 | ((uint16_t)v1 << 8);
            }
        }
    }
    __syncthreads();

    // ---- PV: warp w -> i-tile (w&1), n-quarter (w>>1) ----
    int iw = w & 1, jb = w >> 1;
    int pv[2][4] = {};
    for (int ks = 0; ks < 1024; ks += 32) {
        const int8_t* ap0 = &Asm[(iw * 16 + g) * 1040 + ks + q4 * 4];
        uint32_t a0 = *(const uint32_t*)ap0;
        uint32_t a2 = *(const uint32_t*)(ap0 + 16);
        const int8_t* ap1 = ap0 + 8 * 1040;
        uint32_t a1 = *(const uint32_t*)ap1;
        uint32_t a3 = *(const uint32_t*)(ap1 + 16);
        #pragma unroll
        for (int jj = 0; jj < 2; jj++) {
            const int8_t* bp = &Vsm[(jb * 16 + jj * 8 + g) * 1040 + ks + q4 * 4];
            uint32_t b0 = *(const uint32_t*)bp;
            uint32_t b1 = *(const uint32_t*)(bp + 16);
            MMA_S8(pv[jj], a0, a1, a2, a3, b0, b1);
        }
    }

    // ---- epilogue: quantize x1 ----
    float r9 = g_sc[9];
    #pragma unroll
    for (int jj = 0; jj < 2; jj++) {
        #pragma unroll
        for (int v = 0; v < 4; v++) {
            int rr = qBase + iw * 16 + g + (v >> 1) * 8;
            int cc = jb * 16 + jj * 8 + q4 * 2 + (v & 1);
            g_x1q[((long)(b * SEQ + rr)) * CH + h * HDIM + cc] =
                q8((float)pv[jj][v] * r9);
        }
    }
}

// ---------------- launcher ----------------
extern "C" void kernel_launch(void* const* d_in, const int* in_sizes, int n_in,
                              void* d_out, int out_size) {
    const float* x0             = (const float*)d_in[0];
    const float* qkv_w          = (const float*)d_in[1];
    const float* qkv_b          = (const float*)d_in[2];
    const float* qkv_alpha      = (const float*)d_in[3];
    const float* qkv_act_alpha  = (const float*)d_in[4];
    const float* proj_w         = (const float*)d_in[5];
    const float* proj_b         = (const float*)d_in[6];
    const float* proj_alpha     = (const float*)d_in[7];
    const float* proj_act_alpha = (const float*)d_in[8];
    const float* norm_q_w       = (const float*)d_in[9];
    const float* norm_q_b       = (const float*)d_in[10];
    const float* norm_k_w       = (const float*)d_in[11];
    const float* norm_k_b       = (const float*)d_in[12];
    const float* q_alpha        = (const float*)d_in[13];
    const float* k_alpha        = (const float*)d_in[14];
    const float* v_alpha        = (const float*)d_in[15];
    const float* attn_alpha     = (const float*)d_in[16];
    float* out = (float*)d_out;

    cudaFuncSetAttribute(k_attn_fused, cudaFuncAttributeMaxDynamicSharedMemorySize, SMEM_FUSED);
    cudaFuncSetAttribute(gemm_s8<0>, cudaFuncAttributeMaxDynamicSharedMemorySize, GSM);
    cudaFuncSetAttribute(gemm_s8<1>, cudaFuncAttributeMaxDynamicSharedMemorySize, GSM);

    // 1
    k_pre<<<1, 256>>>(qkv_act_alpha, proj_act_alpha, q_alpha, k_alpha, v_alpha,
                      attn_alpha, qkv_alpha, proj_alpha, qkv_b);
    // 2
    k_quant_all<<<(NG_ALL + 255) / 256, 256>>>(x0, qkv_w, proj_w);
    // 3: QKV GEMM + fused norm -> q2/k2/v2t
    gemm_s8<0><<<dim3(C3v / 128, ROWS / 128, 1), 256, GSM>>>(
        nullptr, qkv_alpha, norm_q_w, norm_q_b, norm_k_w, norm_k_b, nullptr, nullptr);
    // 4 (ncu capture target): single-pass fused attention
    k_attn_fused<<<dim3(SEQ / 32, NBH), 256, SMEM_FUSED>>>();
    // 5: projection GEMM
    gemm_s8<1><<<dim3(CH / 128, ROWS / 128, 1), 256, GSM>>>(
        out, qkv_alpha, norm_q_w, norm_q_b, norm_k_w, norm_k_b, proj_alpha, proj_b);
}

// round 7
// speedup vs baseline: 1.6074x; 1.1171x over previous
#include <cuda_runtime.h>
#include <stdint.h>

// ---------------- problem constants ----------------
constexpr int BATCH = 4, SEQ = 1024, CH = 768, HEADS = 12, HDIM = 64;
constexpr int ROWS = BATCH * SEQ;   // 4096
constexpr int C3v  = 3 * CH;        // 2304
constexpr int NBH  = BATCH * HEADS; // 48

// ---------------- scratch ----------------
__device__ __align__(256) int8_t g_x0q [ROWS * CH];
__device__ __align__(256) int8_t g_wqkv[C3v * CH];
__device__            int    g_biasi[C3v];
__device__ __align__(256) int8_t g_wproj[CH * CH];
__device__ __align__(256) float  g_rw  [C3v + CH];
__device__ __align__(256) int8_t g_q2  [NBH * SEQ * HDIM];
__device__ __align__(256) int8_t g_k2  [NBH * SEQ * HDIM];
__device__ __align__(256) int8_t g_v2t [NBH * HDIM * SEQ];
__device__ __align__(256) int8_t g_x1q [ROWS * CH];
// 0:a_in 1:aq 2:ak 3:av 4:am 5:ap 6:LOG2E*hs*aq*ak 7:am*av 8:1/a_in 9:(am*av)/ap
__device__            float  g_sc[12];

__device__ __forceinline__ float clip8(float x) { return fminf(fmaxf(x, -8.f), 7.f); }
__device__ __forceinline__ int8_t q8(float x) { return (int8_t)__float2int_rn(clip8(x)); }
// attn numerator is >= 0: clip upper bound only
__device__ __forceinline__ int8_t q8p(float x) { return (int8_t)__float2int_rn(fminf(x, 7.f)); }

// 2^floor(e)*(1+frac(e)), e = acc*s6: one FFMA + one F2I
__device__ __forceinline__ float pexp2i(int acc, float s6p) {
    return __int_as_float(__float2int_rn(fmaf((float)acc, s6p, 1065353216.0f)));
}

__device__ __forceinline__ void cp16(void* dst, const void* src) {
    uint32_t d = (uint32_t)__cvta_generic_to_shared(dst);
    asm volatile("cp.async.cg.shared.global [%0], [%1], 16;" :: "r"(d), "l"(src));
}
#define CP_COMMIT() asm volatile("cp.async.commit_group;")
#define CP_WAIT1()  asm volatile("cp.async.wait_group 1;")
#define CP_WAIT0()  asm volatile("cp.async.wait_group 0;")

__device__ __forceinline__ uint32_t smem_u32(const void* p) {
    return (uint32_t)__cvta_generic_to_shared(p);
}
__device__ __forceinline__ void ldsm4(uint32_t addr, uint32_t& r0, uint32_t& r1,
                                      uint32_t& r2, uint32_t& r3) {
    asm volatile("ldmatrix.sync.aligned.m8n8.x4.shared.b16 {%0,%1,%2,%3}, [%4];"
                 : "=r"(r0), "=r"(r1), "=r"(r2), "=r"(r3) : "r"(addr));
}
#define MMA_S8(acc, a0, a1, a2, a3, b0, b1) \
    asm volatile("mma.sync.aligned.m16n8k32.row.col.s32.s8.s8.s32 " \
                 "{%0,%1,%2,%3},{%4,%5,%6,%7},{%8,%9},{%0,%1,%2,%3};" \
                 : "+r"((acc)[0]), "+r"((acc)[1]), "+r"((acc)[2]), "+r"((acc)[3]) \
                 : "r"(a0), "r"(a1), "r"(a2), "r"(a3), "r"(b0), "r"(b1))

// ---------------- pre: scalar means + reciprocals + integer bias ----------------
__global__ void k_pre(const float* __restrict__ qkv_act_alpha,
                      const float* __restrict__ proj_act_alpha,
                      const float* __restrict__ q_alpha,
                      const float* __restrict__ k_alpha,
                      const float* __restrict__ v_alpha,
                      const float* __restrict__ attn_alpha,
                      const float* __restrict__ qkv_alpha,
                      const float* __restrict__ proj_alpha,
                      const float* __restrict__ qkv_b) {
    __shared__ float sh[256];
    int t = threadIdx.x;
    for (int i = t; i < C3v + CH; i += 256)
        g_rw[i] = 1.0f / (i < C3v ? qkv_alpha[i] : proj_alpha[i - C3v]);
    float s = 0.f;
    for (int i = t; i < CH; i += 256) s += qkv_act_alpha[i];
    sh[t] = s; __syncthreads();
    for (int o = 128; o > 0; o >>= 1) { if (t < o) sh[t] += sh[t + o]; __syncthreads(); }
    float a_in = sh[0] / (float)CH;
    __syncthreads();
    for (int o = t; o < C3v; o += 256)
        g_biasi[o] = (int)truncf(qkv_b[o] / a_in / qkv_alpha[o]);
    s = 0.f;
    for (int i = t; i < CH; i += 256) s += proj_act_alpha[i];
    sh[t] = s; __syncthreads();
    for (int o = 128; o > 0; o >>= 1) { if (t < o) sh[t] += sh[t + o]; __syncthreads(); }
    float ap = sh[0] / (float)CH;
    if (t == 0) {
        float aq = 0.f, ak = 0.f, av = 0.f, am = 0.f;
        for (int i = 0; i < HEADS; i++) { aq += q_alpha[i]; ak += k_alpha[i]; av += v_alpha[i]; am += attn_alpha[i]; }
        aq /= HEADS; ak /= HEADS; av /= HEADS; am /= HEADS;
        g_sc[0] = a_in; g_sc[1] = aq; g_sc[2] = ak; g_sc[3] = av; g_sc[4] = am; g_sc[5] = ap;
        g_sc[6] = 1.4426950408889634f * ((0.125f * aq) * ak);
        g_sc[7] = am * av;
        g_sc[8] = 1.0f / a_in;
        g_sc[9] = (am * av) / ap;
    }
}

// ---------------- fused quantizer ----------------
constexpr int NG_X0 = ROWS * CH / 4;
constexpr int NG_WQ = C3v * CH / 4;
constexpr int NG_WP = CH * CH / 4;
constexpr int NG_ALL = NG_X0 + NG_WQ + NG_WP;

__device__ __forceinline__ uint32_t pack4(float a, float b, float c, float d) {
    return (uint32_t)(uint8_t)q8(a) | ((uint32_t)(uint8_t)q8(b) << 8) |
           ((uint32_t)(uint8_t)q8(c) << 16) | ((uint32_t)(uint8_t)q8(d) << 24);
}

__global__ void k_quant_all(const float* __restrict__ x0,
                            const float* __restrict__ qkv_w,
                            const float* __restrict__ proj_w) {
    int i = blockIdx.x * blockDim.x + threadIdx.x;
    if (i >= NG_ALL) return;
    if (i < NG_X0) {
        float r = g_sc[8];
        float4 v = ((const float4*)x0)[i];
        ((uint32_t*)g_x0q)[i] = pack4(v.x * r, v.y * r, v.z * r, v.w * r);
    } else if (i < NG_X0 + NG_WQ) {
        int k = i - NG_X0;
        float r = g_rw[k / (CH / 4)];
        float4 v = ((const float4*)qkv_w)[k];
        ((uint32_t*)g_wqkv)[k] = pack4(v.x * r, v.y * r, v.z * r, v.w * r);
    } else {
        int k = i - NG_X0 - NG_WQ;
        float r = g_rw[C3v + k / (CH / 4)];
        float4 v = ((const float4*)proj_w)[k];
        ((uint32_t*)g_wproj)[k] = pack4(v.x * r, v.y * r, v.z * r, v.w * r);
    }
}

// ---------------- int8 MMA GEMM, 3-stage cp.async, fused norm epilogue (MODE 0) ----------------
constexpr int GSM = 128 * 130 * 4;  // 66560
template <int MODE>
__global__ void __launch_bounds__(256, 2) gemm_s8(float* __restrict__ outf,
        const float* __restrict__ qkv_alpha,
        const float* __restrict__ nqw, const float* __restrict__ nqb,
        const float* __restrict__ nkw, const float* __restrict__ nkb,
        const float* __restrict__ e1, const float* __restrict__ e2) {
    constexpr int K  = 768;
    constexpr int BM = 128, BN = 128, BK = 64;
    constexpr int NTHR = 256;
    constexpr int WM = 64, WN = 32;
    constexpr int MI = 4, NI = 4;
    constexpr int SAS = BK + 16;
    constexpr int NK = K / BK;  // 12

    extern __shared__ __align__(16) int8_t dsm[];
    int8_t* As = dsm;
    int8_t* Bs = dsm + 3 * BM * SAS;

    const int8_t* A  = (MODE == 0) ? g_x0q  : g_x1q;
    const int8_t* Bw = (MODE == 0) ? g_wqkv : g_wproj;

    int tid = threadIdx.x;
    int warp = tid >> 5, lane = tid & 31;
    int wr = warp / 4, wc = warp % 4;
    int g = lane >> 2, q4 = lane & 3;
    int rowBase = blockIdx.y * BM;
    int colBase = blockIdx.x * BN;

    uint32_t As_base = smem_u32(As);
    uint32_t Bs_base = smem_u32(Bs);
    uint32_t aoff = (uint32_t)(wr * WM + (lane & 15)) * SAS + ((lane >> 4) << 4);
    uint32_t boff = (uint32_t)(wc * WN + (lane & 7) + ((lane >> 4) << 3)) * SAS
                    + (((lane >> 3) & 1) << 4);

    auto load_stage = [&](int st, int k0) {
        #pragma unroll
        for (int idx = tid; idx < BM * BK / 16; idx += NTHR) {
            int r = idx / (BK / 16), seg = idx % (BK / 16);
            cp16(&As[st * BM * SAS + r * SAS + seg * 16],
                 &A[(long)(rowBase + r) * K + k0 + seg * 16]);
        }
        #pragma unroll
        for (int idx = tid; idx < BN * BK / 16; idx += NTHR) {
            int r = idx / (BK / 16), seg = idx % (BK / 16);
            cp16(&Bs[st * BN * SAS + r * SAS + seg * 16],
                 &Bw[(long)(colBase + r) * K + k0 + seg * 16]);
        }
    };

    int acc[MI][NI][4];
    #pragma unroll
    for (int i = 0; i < MI; i++)
        #pragma unroll
        for (int j = 0; j < NI; j++)
            #pragma unroll
            for (int v = 0; v < 4; v++) acc[i][j][v] = 0;

    load_stage(0, 0); CP_COMMIT();
    load_stage(1, BK); CP_COMMIT();

    for (int it = 0; it < NK; it++) {
        if (it < NK - 1) { CP_WAIT1(); } else { CP_WAIT0(); }
        __syncthreads();
        if (it + 2 < NK) { load_stage((it + 2) % 3, (it + 2) * BK); CP_COMMIT(); }

        int slot = it % 3;
        uint32_t Abase = As_base + (uint32_t)slot * (BM * SAS) + aoff;
        uint32_t Bbase = Bs_base + (uint32_t)slot * (BN * SAS) + boff;

        #pragma unroll
        for (int ks = 0; ks < BK; ks += 32) {
            uint32_t bfr[2][4];
            #pragma unroll
            for (int jj = 0; jj < 2; jj++)
                ldsm4(Bbase + jj * (16 * SAS) + ks,
                      bfr[jj][0], bfr[jj][1], bfr[jj][2], bfr[jj][3]);
            #pragma unroll
            for (int i = 0; i < MI; i++) {
                uint32_t a0, a1, a2, a3;
                ldsm4(Abase + i * (16 * SAS) + ks, a0, a1, a2, a3);
                #pragma unroll
                for (int j = 0; j < NI; j++)
                    MMA_S8(acc[i][j], a0, a1, a2, a3,
                           bfr[j >> 1][(j & 1) * 2], bfr[j >> 1][(j & 1) * 2 + 1]);
            }
        }
    }
    __syncthreads();

    if constexpr (MODE == 1) {
        float s5 = g_sc[5];
        int rb = rowBase + wr * WM;
        int cb = colBase + wc * WN;
        #pragma unroll
        for (int i = 0; i < MI; i++)
            #pragma unroll
            for (int j = 0; j < NI; j++)
                #pragma unroll
                for (int v = 0; v < 4; v++) {
                    int rr = rb + i * 16 + g + (v >> 1) * 8;
                    int cc = cb + j * 8 + q4 * 2 + (v & 1);
                    outf[(long)rr * CH + cc] = ((float)acc[i][j][v] * e1[cc]) * s5 + e2[cc];
                }
    } else {
        __shared__ float sA[130], sP1[130], sP2[130];
        __shared__ int   sBi[130], coef[64];
        int* sm32 = (int*)dsm;

        if (tid < 128) {
            int col = colBase + tid;
            int d = tid & 63, hs = tid >> 6;
            int idx = d * 2 + hs;
            int branch = col / CH;
            sBi[idx] = g_biasi[col];
            if (branch == 0) {
                float w = nqw[d];
                sA[idx]  = qkv_alpha[col];
                sP1[idx] = nqb[d] / w;
                sP2[idx] = w / g_sc[1];
            } else if (branch == 1) {
                float w = nkw[d];
                sA[idx]  = qkv_alpha[col];
                sP1[idx] = nkb[d] / w;
                sP2[idx] = w / g_sc[2];
            } else {
                sA[idx]  = (g_sc[0] * qkv_alpha[col]) / g_sc[3];
                sP1[idx] = 0.f; sP2[idx] = 0.f;
            }
        }
        if (tid < 64) coef[tid] = 1024 / (tid + 1);

        int rbL = wr * WM, cbL = wc * WN;
        #pragma unroll
        for (int i = 0; i < MI; i++)
            #pragma unroll
            for (int j = 0; j < NI; j++)
                #pragma unroll
                for (int v = 0; v < 4; v++) {
                    int rr = rbL + i * 16 + g + (v >> 1) * 8;
                    int cc = cbL + j * 8 + q4 * 2 + (v & 1);
                    sm32[rr * 130 + cc + (cc >> 6)] = acc[i][j][v];
                }
        __syncthreads();

        int r = tid >> 1, hs = tid & 1;
        int slice = (colBase >> 6) + hs;
        int branch = slice / HEADS;
        int hh = slice % HEADS;
        int rrG = rowBase + r;
        int bb = rrG >> 10, nn = rrG & 1023;
        int bhh = bb * HEADS + hh;
        const int base = r * 130 + hs * 65;

        if (branch < 2) {
            int m = 0, vv = 0;
            #pragma unroll 8
            for (int d = 0; d < HDIM; d++) {
                int ival = sm32[base + d] + sBi[d * 2 + hs];
                float xf = (float)ival * sA[d * 2 + hs];
                int xi = (int)xf;
                int dd = xi - m;
                m += (dd * coef[d]) >> 10;
                vv += dd * (xi - m);
            }
            float mu = (float)m;
            float invden = 1.0f / (sqrtf((float)vv * 0.015625f) + 1e-5f);
            uint32_t* outp = (uint32_t*)((branch == 0 ? g_q2 : g_k2)
                              + ((long)bhh * SEQ + nn) * HDIM);
            #pragma unroll 4
            for (int dw = 0; dw < 16; dw++) {
                uint32_t pk = 0;
                #pragma unroll
                for (int kk = 0; kk < 4; kk++) {
                    int d = dw * 4 + kk;
                    int ival = sm32[base + d] + sBi[d * 2 + hs];
                    float xf = (float)ival * sA[d * 2 + hs];
                    float q1 = (xf - mu) * invden;
                    pk |= ((uint32_t)(uint8_t)q8((q1 + sP1[d * 2 + hs]) * sP2[d * 2 + hs]))
                          << (kk * 8);
                }
                outp[dw] = pk;
            }
        } else {
            int8_t* outv = g_v2t + (long)bhh * HDIM * SEQ + nn;
            #pragma unroll 8
            for (int d = 0; d < HDIM; d++) {
                int ival = sm32[base + d] + sBi[d * 2 + hs];
                outv[d * SEQ] = q8((float)ival * sA[d * 2 + hs]);
            }
        }
    }
}

// ---------------- single-pass fused flash attention, 2 CTAs/SM ----------------
// grid (SEQ/16, NBH), 256 threads. Q tile = 16 rows; 16x1024 scores in regs
// (64/thread). K streamed in 2 halves and V in 2 halves through one 40KB buffer.
constexpr int ATT_KV = 0;        // 512*80 = 40960 (K halves); V halves 64*528 = 33792
constexpr int ATT_A  = 40960;    // 16 * 1040 = 16640
constexpr int ATT_Q  = 57600;    // 16 * 80 = 1280
constexpr int ATT_S  = 58880;    // 16 floats
constexpr int SMEM_ATT = 58944;

__global__ void __launch_bounds__(256, 2) k_attn_fused() {
    extern __shared__ __align__(16) int8_t sh[];
    int8_t* KV  = sh + ATT_KV;
    int8_t* Asm = sh + ATT_A;
    int8_t* Qsm = sh + ATT_Q;
    float*  rs  = (float*)(sh + ATT_S);

    int bh = blockIdx.y, b = bh / HEADS, h = bh % HEADS;
    int qBase = blockIdx.x * 16;
    int tid = threadIdx.x, w = tid >> 5, lane = tid & 31;
    int g = lane >> 2, q4 = lane & 3;

    const int8_t* Qg = g_q2 + ((long)bh * SEQ + qBase) * HDIM;
    const int8_t* Kg = g_k2 + (long)bh * SEQ * HDIM;
    const int8_t* Vg = g_v2t + (long)bh * HDIM * SEQ;

    // load Q (16x64) + K half0 (rows 0..511)
    if (tid < 64) {
        int r = tid >> 2, s = tid & 3;
        cp16(&Qsm[r * 80 + s * 16], &Qg[r * 64 + s * 16]);
    }
    for (int idx = tid; idx < 2048; idx += 256) {
        int r = idx >> 2, s = idx & 3;
        cp16(&KV[r * 80 + s * 16], &Kg[r * 64 + s * 16]);
    }
    CP_COMMIT();
    if (tid < 16) rs[tid] = 0.f;
    CP_WAIT0();
    __syncthreads();

    // Q operand fragments (fixed for whole kernel)
    uint32_t aq[2][4];
    #pragma unroll
    for (int ks2 = 0; ks2 < 2; ks2++) {
        const int8_t* ap0 = &Qsm[g * 80 + ks2 * 32 + q4 * 4];
        aq[ks2][0] = *(const uint32_t*)ap0;
        aq[ks2][2] = *(const uint32_t*)(ap0 + 16);
        const int8_t* ap1 = ap0 + 8 * 80;
        aq[ks2][1] = *(const uint32_t*)ap1;
        aq[ks2][3] = *(const uint32_t*)(ap1 + 16);
    }

    int acc[16][4];
    #pragma unroll
    for (int j = 0; j < 16; j++)
        #pragma unroll
        for (int v = 0; v < 4; v++) acc[j][v] = 0;

    // ---- QK over two K halves; warp w covers cols h*512 + w*64 + jl*8 ----
    #pragma unroll
    for (int half = 0; half < 2; half++) {
        if (half == 1) {
            __syncthreads();   // all warps done reading K half0
            for (int idx = tid; idx < 2048; idx += 256) {
                int r = idx >> 2, s = idx & 3;
                cp16(&KV[r * 80 + s * 16], &Kg[(512 + r) * 64 + s * 16]);
            }
            CP_COMMIT(); CP_WAIT0();
            __syncthreads();
        }
        #pragma unroll
        for (int jl = 0; jl < 8; jl++) {
            int* a = acc[half * 8 + jl];
            #pragma unroll
            for (int ks2 = 0; ks2 < 2; ks2++) {
                const int8_t* bp = &KV[(w * 64 + jl * 8 + g) * 80 + ks2 * 32 + q4 * 4];
                uint32_t b0 = *(const uint32_t*)bp;
                uint32_t b1 = *(const uint32_t*)(bp + 16);
                MMA_S8(a, aq[ks2][0], aq[ks2][1], aq[ks2][2], aq[ks2][3], b0, b1);
            }
        }
    }
    __syncthreads();   // done reading K half1

    // prefetch V half0 (cols 0..511) into the same buffer
    for (int idx = tid; idx < 2048; idx += 256) {
        int d = idx >> 5, s = idx & 31;
        cp16(&KV[d * 528 + s * 16], &Vg[d * 1024 + s * 16]);
    }
    CP_COMMIT();

    // ---- softmax: convert scores to exp2 numerators in-place, row sums ----
    float s6p = g_sc[6] * 8388608.0f;
    float sum0 = 0.f, sum1 = 0.f;
    #pragma unroll
    for (int j = 0; j < 16; j++) {
        float p0 = pexp2i(acc[j][0], s6p);
        float p1 = pexp2i(acc[j][1], s6p);
        float p2 = pexp2i(acc[j][2], s6p);
        float p3 = pexp2i(acc[j][3], s6p);
        acc[j][0] = __float_as_int(p0); acc[j][1] = __float_as_int(p1);
        acc[j][2] = __float_as_int(p2); acc[j][3] = __float_as_int(p3);
        sum0 += p0 + p1;
        sum1 += p2 + p3;
    }
    sum0 += __shfl_xor_sync(0xffffffffu, sum0, 1);
    sum0 += __shfl_xor_sync(0xffffffffu, sum0, 2);
    sum1 += __shfl_xor_sync(0xffffffffu, sum1, 1);
    sum1 += __shfl_xor_sync(0xffffffffu, sum1, 2);
    if (q4 == 0) {
        atomicAdd(&rs[g], sum0);
        atomicAdd(&rs[g + 8], sum1);
    }
    __syncthreads();
    if (tid < 16) rs[tid] = 1.0f / (rs[tid] * g_sc[4]);
    __syncthreads();

    // ---- quantize attn into Asm ----
    float iv0 = rs[g], iv1 = rs[g + 8];
    #pragma unroll
    for (int j = 0; j < 16; j++) {
        int col = (j >> 3) * 512 + w * 64 + (j & 7) * 8 + q4 * 2;
        uint8_t v0 = (uint8_t)q8p(__int_as_float(acc[j][0]) * iv0);
        uint8_t v1 = (uint8_t)q8p(__int_as_float(acc[j][1]) * iv0);
        *(uint16_t*)&Asm[g * 1040 + col] = (uint16_t)v0 | ((uint16_t)v1 << 8);
        uint8_t v2 = (uint8_t)q8p(__int_as_float(acc[j][2]) * iv1);
        uint8_t v3 = (uint8_t)q8p(__int_as_float(acc[j][3]) * iv1);
        *(uint16_t*)&Asm[(g + 8) * 1040 + col] = (uint16_t)v2 | ((uint16_t)v3 << 8);
    }
    __syncthreads();
    CP_WAIT0();        // V half0 landed
    __syncthreads();

    // ---- PV over two V halves; warp w covers output cols w*8..w*8+7 ----
    int pv[4] = {0, 0, 0, 0};
    #pragma unroll
    for (int half = 0; half < 2; half++) {
        if (half == 1) {
            __syncthreads();   // done reading V half0
            for (int idx = tid; idx < 2048; idx += 256) {
                int d = idx >> 5, s = idx & 31;
                cp16(&KV[d * 528 + s * 16], &Vg[d * 1024 + 512 + s * 16]);
            }
            CP_COMMIT(); CP_WAIT0();
            __syncthreads();
        }
        #pragma unroll 4
        for (int ksl = 0; ksl < 512; ksl += 32) {
            const int8_t* ap0 = &Asm[g * 1040 + half * 512 + ksl + q4 * 4];
            uint32_t a0 = *(const uint32_t*)ap0;
            uint32_t a2 = *(const uint32_t*)(ap0 + 16);
            const int8_t* ap1 = ap0 + 8 * 1040;
            uint32_t a1 = *(const uint32_t*)ap1;
            uint32_t a3 = *(const uint32_t*)(ap1 + 16);
            const int8_t* bp = &KV[(w * 8 + g) * 528 + ksl + q4 * 4];
            uint32_t b0 = *(const uint32_t*)bp;
            uint32_t b1 = *(const uint32_t*)(bp + 16);
            MMA_S8(pv, a0, a1, a2, a3, b0, b1);
        }
    }

    // ---- epilogue ----
    float r9 = g_sc[9];
    #pragma unroll
    for (int v = 0; v < 4; v++) {
        int rr = qBase + g + (v >> 1) * 8;
        int cc = w * 8 + q4 * 2 + (v & 1);
        g_x1q[((long)(b * SEQ + rr)) * CH + h * HDIM + cc] = q8((float)pv[v] * r9);
    }
}

// ---------------- launcher ----------------
extern "C" void kernel_launch(void* const* d_in, const int* in_sizes, int n_in,
                              void* d_out, int out_size) {
    const float* x0             = (const float*)d_in[0];
    const float* qkv_w          = (const float*)d_in[1];
    const float* qkv_b          = (const float*)d_in[2];
    const float* qkv_alpha      = (const float*)d_in[3];
    const float* qkv_act_alpha  = (const float*)d_in[4];
    const float* proj_w         = (const float*)d_in[5];
    const float* proj_b         = (const float*)d_in[6];
    const float* proj_alpha     = (const float*)d_in[7];
    const float* proj_act_alpha = (const float*)d_in[8];
    const float* norm_q_w       = (const float*)d_in[9];
    const float* norm_q_b       = (const float*)d_in[10];
    const float* norm_k_w       = (const float*)d_in[11];
    const float* norm_k_b       = (const float*)d_in[12];
    const float* q_alpha        = (const float*)d_in[13];
    const float* k_alpha        = (const float*)d_in[14];
    const float* v_alpha        = (const float*)d_in[15];
    const float* attn_alpha     = (const float*)d_in[16];
    float* out = (float*)d_out;

    cudaFuncSetAttribute(k_attn_fused, cudaFuncAttributeMaxDynamicSharedMemorySize, SMEM_ATT);
    cudaFuncSetAttribute(gemm_s8<0>, cudaFuncAttributeMaxDynamicSharedMemorySize, GSM);
    cudaFuncSetAttribute(gemm_s8<1>, cudaFuncAttributeMaxDynamicSharedMemorySize, GSM);

    // 1
    k_pre<<<1, 256>>>(qkv_act_alpha, proj_act_alpha, q_alpha, k_alpha, v_alpha,
                      attn_alpha, qkv_alpha, proj_alpha, qkv_b);
    // 2
    k_quant_all<<<(NG_ALL + 255) / 256, 256>>>(x0, qkv_w, proj_w);
    // 3: QKV GEMM + fused norm -> q2/k2/v2t
    gemm_s8<0><<<dim3(C3v / 128, ROWS / 128, 1), 256, GSM>>>(
        nullptr, qkv_alpha, norm_q_w, norm_q_b, norm_k_w, norm_k_b, nullptr, nullptr);
    // 4 (ncu capture target): fused attention, 2 CTAs/SM
    k_attn_fused<<<dim3(SEQ / 16, NBH), 256, SMEM_ATT>>>();
    // 5: projection GEMM
    gemm_s8<1><<<dim3(CH / 128, ROWS / 128, 1), 256, GSM>>>(
        out, qkv_alpha, norm_q_w, norm_q_b, norm_k_w, norm_k_b, proj_alpha, proj_b);
}

// round 8
// speedup vs baseline: 1.7818x; 1.1085x over previous
#include <cuda_runtime.h>
#include <stdint.h>

// ---------------- problem constants ----------------
constexpr int BATCH = 4, SEQ = 1024, CH = 768, HEADS = 12, HDIM = 64;
constexpr int ROWS = BATCH * SEQ;   // 4096
constexpr int C3v  = 3 * CH;        // 2304
constexpr int NBH  = BATCH * HEADS; // 48

// ---------------- scratch ----------------
__device__ __align__(256) int8_t g_x0q [ROWS * CH];
__device__ __align__(256) int8_t g_wqkv[C3v * CH];
__device__            int    g_biasi[C3v];
__device__ __align__(256) int8_t g_wproj[CH * CH];
__device__ __align__(256) float  g_rw  [C3v + CH];
__device__ __align__(256) int8_t g_q2  [NBH * SEQ * HDIM];
__device__ __align__(256) int8_t g_k2  [NBH * SEQ * HDIM];
__device__ __align__(256) int8_t g_v2t [NBH * HDIM * SEQ];
__device__ __align__(256) int8_t g_x1q [ROWS * CH];
// 0:a_in 1:aq 2:ak 3:av 4:am 5:ap 6:LOG2E*hs*aq*ak 7:am*av 8:1/a_in 9:(am*av)/ap
__device__            float  g_sc[12];

__device__ __forceinline__ float clip8(float x) { return fminf(fmaxf(x, -8.f), 7.f); }
__device__ __forceinline__ int8_t q8(float x) { return (int8_t)__float2int_rn(clip8(x)); }
// attn numerator >= 0: upper clip only
__device__ __forceinline__ int8_t q8p(float x) { return (int8_t)__float2int_rn(fminf(x, 7.f)); }

// 2^floor(e)*(1+frac(e)), e = acc*s6: one FFMA + one F2I
__device__ __forceinline__ float pexp2i(int acc, float s6p) {
    return __int_as_float(__float2int_rn(fmaf((float)acc, s6p, 1065353216.0f)));
}

__device__ __forceinline__ void cp16(void* dst, const void* src) {
    uint32_t d = (uint32_t)__cvta_generic_to_shared(dst);
    asm volatile("cp.async.cg.shared.global [%0], [%1], 16;" :: "r"(d), "l"(src));
}
#define CP_COMMIT() asm volatile("cp.async.commit_group;")
#define CP_WAIT1()  asm volatile("cp.async.wait_group 1;")
#define CP_WAIT0()  asm volatile("cp.async.wait_group 0;")

__device__ __forceinline__ uint32_t smem_u32(const void* p) {
    return (uint32_t)__cvta_generic_to_shared(p);
}
__device__ __forceinline__ void ldsm4(uint32_t addr, uint32_t& r0, uint32_t& r1,
                                      uint32_t& r2, uint32_t& r3) {
    asm volatile("ldmatrix.sync.aligned.m8n8.x4.shared.b16 {%0,%1,%2,%3}, [%4];"
                 : "=r"(r0), "=r"(r1), "=r"(r2), "=r"(r3) : "r"(addr));
}
#define MMA_S8(acc, a0, a1, a2, a3, b0, b1) \
    asm volatile("mma.sync.aligned.m16n8k32.row.col.s32.s8.s8.s32 " \
                 "{%0,%1,%2,%3},{%4,%5,%6,%7},{%8,%9},{%0,%1,%2,%3};" \
                 : "+r"((acc)[0]), "+r"((acc)[1]), "+r"((acc)[2]), "+r"((acc)[3]) \
                 : "r"(a0), "r"(a1), "r"(a2), "r"(a3), "r"(b0), "r"(b1))

// ---------------- pre: scalar means + reciprocals + integer bias ----------------
__global__ void k_pre(const float* __restrict__ qkv_act_alpha,
                      const float* __restrict__ proj_act_alpha,
                      const float* __restrict__ q_alpha,
                      const float* __restrict__ k_alpha,
                      const float* __restrict__ v_alpha,
                      const float* __restrict__ attn_alpha,
                      const float* __restrict__ qkv_alpha,
                      const float* __restrict__ proj_alpha,
                      const float* __restrict__ qkv_b) {
    __shared__ float sh[256];
    int t = threadIdx.x;
    for (int i = t; i < C3v + CH; i += 256)
        g_rw[i] = 1.0f / (i < C3v ? qkv_alpha[i] : proj_alpha[i - C3v]);
    float s = 0.f;
    for (int i = t; i < CH; i += 256) s += qkv_act_alpha[i];
    sh[t] = s; __syncthreads();
    for (int o = 128; o > 0; o >>= 1) { if (t < o) sh[t] += sh[t + o]; __syncthreads(); }
    float a_in = sh[0] / (float)CH;
    __syncthreads();
    for (int o = t; o < C3v; o += 256)
        g_biasi[o] = (int)truncf(qkv_b[o] / a_in / qkv_alpha[o]);
    s = 0.f;
    for (int i = t; i < CH; i += 256) s += proj_act_alpha[i];
    sh[t] = s; __syncthreads();
    for (int o = 128; o > 0; o >>= 1) { if (t < o) sh[t] += sh[t + o]; __syncthreads(); }
    float ap = sh[0] / (float)CH;
    if (t == 0) {
        float aq = 0.f, ak = 0.f, av = 0.f, am = 0.f;
        for (int i = 0; i < HEADS; i++) { aq += q_alpha[i]; ak += k_alpha[i]; av += v_alpha[i]; am += attn_alpha[i]; }
        aq /= HEADS; ak /= HEADS; av /= HEADS; am /= HEADS;
        g_sc[0] = a_in; g_sc[1] = aq; g_sc[2] = ak; g_sc[3] = av; g_sc[4] = am; g_sc[5] = ap;
        g_sc[6] = 1.4426950408889634f * ((0.125f * aq) * ak);
        g_sc[7] = am * av;
        g_sc[8] = 1.0f / a_in;
        g_sc[9] = (am * av) / ap;
    }
}

// ---------------- fused quantizer ----------------
constexpr int NG_X0 = ROWS * CH / 4;
constexpr int NG_WQ = C3v * CH / 4;
constexpr int NG_WP = CH * CH / 4;
constexpr int NG_ALL = NG_X0 + NG_WQ + NG_WP;

__device__ __forceinline__ uint32_t pack4(float a, float b, float c, float d) {
    return (uint32_t)(uint8_t)q8(a) | ((uint32_t)(uint8_t)q8(b) << 8) |
           ((uint32_t)(uint8_t)q8(c) << 16) | ((uint32_t)(uint8_t)q8(d) << 24);
}

__global__ void k_quant_all(const float* __restrict__ x0,
                            const float* __restrict__ qkv_w,
                            const float* __restrict__ proj_w) {
    int i = blockIdx.x * blockDim.x + threadIdx.x;
    if (i >= NG_ALL) return;
    if (i < NG_X0) {
        float r = g_sc[8];
        float4 v = ((const float4*)x0)[i];
        ((uint32_t*)g_x0q)[i] = pack4(v.x * r, v.y * r, v.z * r, v.w * r);
    } else if (i < NG_X0 + NG_WQ) {
        int k = i - NG_X0;
        float r = g_rw[k / (CH / 4)];
        float4 v = ((const float4*)qkv_w)[k];
        ((uint32_t*)g_wqkv)[k] = pack4(v.x * r, v.y * r, v.z * r, v.w * r);
    } else {
        int k = i - NG_X0 - NG_WQ;
        float r = g_rw[C3v + k / (CH / 4)];
        float4 v = ((const float4*)proj_w)[k];
        ((uint32_t*)g_wproj)[k] = pack4(v.x * r, v.y * r, v.z * r, v.w * r);
    }
}

// ---------------- int8 MMA GEMM, 3-stage cp.async ----------------
// MODE 0: qkv 128x128 tile, fused norm epilogue -> g_q2/g_k2/g_v2t
// MODE 1: proj 128x64 tile -> d_out fp32
constexpr int GSM0 = 128 * 130 * 4;                 // 66560 (epilogue tile dominates)
constexpr int GSM1 = 3 * (128 + 64) * 80;           // 46080
template <int MODE>
__global__ void __launch_bounds__(256, 2) gemm_s8(float* __restrict__ outf,
        const float* __restrict__ qkv_alpha,
        const float* __restrict__ nqw, const float* __restrict__ nqb,
        const float* __restrict__ nkw, const float* __restrict__ nkb,
        const float* __restrict__ e1, const float* __restrict__ e2) {
    constexpr int K  = 768;
    constexpr int BM = 128;
    constexpr int BN = (MODE == 0) ? 128 : 64;
    constexpr int BK = 64;
    constexpr int NTHR = 256;
    constexpr int WM = 64, WN = BN / 4;
    constexpr int MI = 4, NI = WN / 8;
    constexpr int SAS = BK + 16;
    constexpr int NK = K / BK;  // 12

    extern __shared__ __align__(16) int8_t dsm[];
    int8_t* As = dsm;
    int8_t* Bs = dsm + 3 * BM * SAS;

    const int8_t* A  = (MODE == 0) ? g_x0q  : g_x1q;
    const int8_t* Bw = (MODE == 0) ? g_wqkv : g_wproj;

    int tid = threadIdx.x;
    int warp = tid >> 5, lane = tid & 31;
    int wr = warp / 4, wc = warp % 4;
    int g = lane >> 2, q4 = lane & 3;
    int rowBase = blockIdx.y * BM;
    int colBase = blockIdx.x * BN;

    uint32_t As_base = smem_u32(As);
    uint32_t Bs_base = smem_u32(Bs);
    uint32_t aoff = (uint32_t)(wr * WM + (lane & 15)) * SAS + ((lane >> 4) << 4);
    uint32_t boff = (uint32_t)(wc * WN + (lane & 7) + ((lane >> 4) << 3)) * SAS
                    + (((lane >> 3) & 1) << 4);

    auto load_stage = [&](int st, int k0) {
        #pragma unroll
        for (int idx = tid; idx < BM * BK / 16; idx += NTHR) {
            int r = idx / (BK / 16), seg = idx % (BK / 16);
            cp16(&As[st * BM * SAS + r * SAS + seg * 16],
                 &A[(long)(rowBase + r) * K + k0 + seg * 16]);
        }
        #pragma unroll
        for (int idx = tid; idx < BN * BK / 16; idx += NTHR) {
            int r = idx / (BK / 16), seg = idx % (BK / 16);
            cp16(&Bs[st * BN * SAS + r * SAS + seg * 16],
                 &Bw[(long)(colBase + r) * K + k0 + seg * 16]);
        }
    };

    int acc[MI][NI][4];
    #pragma unroll
    for (int i = 0; i < MI; i++)
        #pragma unroll
        for (int j = 0; j < NI; j++)
            #pragma unroll
            for (int v = 0; v < 4; v++) acc[i][j][v] = 0;

    load_stage(0, 0); CP_COMMIT();
    load_stage(1, BK); CP_COMMIT();

    for (int it = 0; it < NK; it++) {
        if (it < NK - 1) { CP_WAIT1(); } else { CP_WAIT0(); }
        __syncthreads();
        if (it + 2 < NK) { load_stage((it + 2) % 3, (it + 2) * BK); CP_COMMIT(); }

        int slot = it % 3;
        uint32_t Abase = As_base + (uint32_t)slot * (BM * SAS) + aoff;
        uint32_t Bbase = Bs_base + (uint32_t)slot * (BN * SAS) + boff;

        #pragma unroll
        for (int ks = 0; ks < BK; ks += 32) {
            uint32_t bfr[(NI + 1) / 2][4];
            #pragma unroll
            for (int jj = 0; jj < (NI + 1) / 2; jj++)
                ldsm4(Bbase + jj * (16 * SAS) + ks,
                      bfr[jj][0], bfr[jj][1], bfr[jj][2], bfr[jj][3]);
            #pragma unroll
            for (int i = 0; i < MI; i++) {
                uint32_t a0, a1, a2, a3;
                ldsm4(Abase + i * (16 * SAS) + ks, a0, a1, a2, a3);
                #pragma unroll
                for (int j = 0; j < NI; j++)
                    MMA_S8(acc[i][j], a0, a1, a2, a3,
                           bfr[j >> 1][(j & 1) * 2], bfr[j >> 1][(j & 1) * 2 + 1]);
            }
        }
    }
    __syncthreads();

    if constexpr (MODE == 1) {
        float s5 = g_sc[5];
        int rb = rowBase + wr * WM;
        int cb = colBase + wc * WN;
        #pragma unroll
        for (int i = 0; i < MI; i++)
            #pragma unroll
            for (int j = 0; j < NI; j++)
                #pragma unroll
                for (int v = 0; v < 4; v++) {
                    int rr = rb + i * 16 + g + (v >> 1) * 8;
                    int cc = cb + j * 8 + q4 * 2 + (v & 1);
                    outf[(long)rr * CH + cc] = ((float)acc[i][j][v] * e1[cc]) * s5 + e2[cc];
                }
    } else {
        __shared__ float sA[130], sP1[130], sP2[130];
        __shared__ int   sBi[130], coef[64];
        int* sm32 = (int*)dsm;

        if (tid < 128) {
            int col = colBase + tid;
            int d = tid & 63, hs = tid >> 6;
            int idx = d * 2 + hs;
            int branch = col / CH;
            sBi[idx] = g_biasi[col];
            if (branch == 0) {
                float w = nqw[d];
                sA[idx]  = qkv_alpha[col];
                sP1[idx] = nqb[d] / w;
                sP2[idx] = w / g_sc[1];
            } else if (branch == 1) {
                float w = nkw[d];
                sA[idx]  = qkv_alpha[col];
                sP1[idx] = nkb[d] / w;
                sP2[idx] = w / g_sc[2];
            } else {
                sA[idx]  = (g_sc[0] * qkv_alpha[col]) / g_sc[3];
                sP1[idx] = 0.f; sP2[idx] = 0.f;
            }
        }
        if (tid < 64) coef[tid] = 1024 / (tid + 1);

        int rbL = wr * WM, cbL = wc * WN;
        #pragma unroll
        for (int i = 0; i < MI; i++)
            #pragma unroll
            for (int j = 0; j < NI; j++)
                #pragma unroll
                for (int v = 0; v < 4; v++) {
                    int rr = rbL + i * 16 + g + (v >> 1) * 8;
                    int cc = cbL + j * 8 + q4 * 2 + (v & 1);
                    sm32[rr * 130 + cc + (cc >> 6)] = acc[i][j][v];
                }
        __syncthreads();

        int r = tid >> 1, hs = tid & 1;
        int slice = (colBase >> 6) + hs;
        int branch = slice / HEADS;
        int hh = slice % HEADS;
        int rrG = rowBase + r;
        int bb = rrG >> 10, nn = rrG & 1023;
        int bhh = bb * HEADS + hh;
        const int base = r * 130 + hs * 65;

        if (branch < 2) {
            int m = 0, vv = 0;
            #pragma unroll 8
            for (int d = 0; d < HDIM; d++) {
                int ival = sm32[base + d] + sBi[d * 2 + hs];
                float xf = (float)ival * sA[d * 2 + hs];
                int xi = (int)xf;
                int dd = xi - m;
                m += (dd * coef[d]) >> 10;
                vv += dd * (xi - m);
            }
            float mu = (float)m;
            float invden = 1.0f / (sqrtf((float)vv * 0.015625f) + 1e-5f);
            uint32_t* outp = (uint32_t*)((branch == 0 ? g_q2 : g_k2)
                              + ((long)bhh * SEQ + nn) * HDIM);
            #pragma unroll 4
            for (int dw = 0; dw < 16; dw++) {
                uint32_t pk = 0;
                #pragma unroll
                for (int kk = 0; kk < 4; kk++) {
                    int d = dw * 4 + kk;
                    int ival = sm32[base + d] + sBi[d * 2 + hs];
                    float xf = (float)ival * sA[d * 2 + hs];
                    float q1 = (xf - mu) * invden;
                    pk |= ((uint32_t)(uint8_t)q8((q1 + sP1[d * 2 + hs]) * sP2[d * 2 + hs]))
                          << (kk * 8);
                }
                outp[dw] = pk;
            }
        } else {
            int8_t* outv = g_v2t + (long)bhh * HDIM * SEQ + nn;
            #pragma unroll 8
            for (int d = 0; d < HDIM; d++) {
                int ival = sm32[base + d] + sBi[d * 2 + hs];
                outv[d * SEQ] = q8((float)ival * sA[d * 2 + hs]);
            }
        }
    }
}

// ---------------- single-pass fused flash attention, double-buffered K/V, 2 CTAs/SM ----
// grid (SEQ/16, NBH), 256 threads. 16x1024 scores in regs (64/thread).
// K half h -> KVh buffer (512 rows x 80B); then V half h -> KVh (64 rows x 528B).
constexpr int ATT_KV0 = 0;          // 40960
constexpr int ATT_KV1 = 40960;      // 40960
constexpr int ATT_A   = 81920;      // 16 * 1040 = 16640
constexpr int ATT_Q   = 98560;      // 1280
constexpr int ATT_S   = 99840;      // 64
constexpr int SMEM_ATT = 99904;

__global__ void __launch_bounds__(256, 2) k_attn_fused() {
    extern __shared__ __align__(16) int8_t sh[];
    int8_t* KV0 = sh + ATT_KV0;
    int8_t* KV1 = sh + ATT_KV1;
    int8_t* Asm = sh + ATT_A;
    int8_t* Qsm = sh + ATT_Q;
    float*  rs  = (float*)(sh + ATT_S);

    int bh = blockIdx.y, b = bh / HEADS, h = bh % HEADS;
    int qBase = blockIdx.x * 16;
    int tid = threadIdx.x, w = tid >> 5, lane = tid & 31;
    int g = lane >> 2, q4 = lane & 3;

    const int8_t* Qg = g_q2 + ((long)bh * SEQ + qBase) * HDIM;
    const int8_t* Kg = g_k2 + (long)bh * SEQ * HDIM;
    const int8_t* Vg = g_v2t + (long)bh * HDIM * SEQ;

    // group A: Q + K half0 ; group B: K half1
    if (tid < 64) {
        int r = tid >> 2, s = tid & 3;
        cp16(&Qsm[r * 80 + s * 16], &Qg[r * 64 + s * 16]);
    }
    for (int idx = tid; idx < 2048; idx += 256) {
        int r = idx >> 2, s = idx & 3;
        cp16(&KV0[r * 80 + s * 16], &Kg[r * 64 + s * 16]);
    }
    CP_COMMIT();
    for (int idx = tid; idx < 2048; idx += 256) {
        int r = idx >> 2, s = idx & 3;
        cp16(&KV1[r * 80 + s * 16], &Kg[(512 + r) * 64 + s * 16]);
    }
    CP_COMMIT();
    if (tid < 16) rs[tid] = 0.f;
    CP_WAIT1();        // Q + K0 landed
    __syncthreads();

    // Q operand fragments (fixed for whole kernel)
    uint32_t aq[2][4];
    #pragma unroll
    for (int ks2 = 0; ks2 < 2; ks2++) {
        const int8_t* ap0 = &Qsm[g * 80 + ks2 * 32 + q4 * 4];
        aq[ks2][0] = *(const uint32_t*)ap0;
        aq[ks2][2] = *(const uint32_t*)(ap0 + 16);
        const int8_t* ap1 = ap0 + 8 * 80;
        aq[ks2][1] = *(const uint32_t*)ap1;
        aq[ks2][3] = *(const uint32_t*)(ap1 + 16);
    }

    int acc[16][4];
    #pragma unroll
    for (int j = 0; j < 16; j++)
        #pragma unroll
        for (int v = 0; v < 4; v++) acc[j][v] = 0;

    // ---- QK half0 (KV0) ----
    #pragma unroll
    for (int jl = 0; jl < 8; jl++) {
        int* a = acc[jl];
        #pragma unroll
        for (int ks2 = 0; ks2 < 2; ks2++) {
            const int8_t* bp = &KV0[(w * 64 + jl * 8 + g) * 80 + ks2 * 32 + q4 * 4];
            uint32_t b0 = *(const uint32_t*)bp;
            uint32_t b1 = *(const uint32_t*)(bp + 16);
            MMA_S8(a, aq[ks2][0], aq[ks2][1], aq[ks2][2], aq[ks2][3], b0, b1);
        }
    }
    CP_WAIT0();        // K1 landed (loaded while QK0 ran)
    __syncthreads();
    // ---- QK half1 (KV1) ----
    #pragma unroll
    for (int jl = 0; jl < 8; jl++) {
        int* a = acc[8 + jl];
        #pragma unroll
        for (int ks2 = 0; ks2 < 2; ks2++) {
            const int8_t* bp = &KV1[(w * 64 + jl * 8 + g) * 80 + ks2 * 32 + q4 * 4];
            uint32_t b0 = *(const uint32_t*)bp;
            uint32_t b1 = *(const uint32_t*)(bp + 16);
            MMA_S8(a, aq[ks2][0], aq[ks2][1], aq[ks2][2], aq[ks2][3], b0, b1);
        }
    }
    __syncthreads();   // all warps done reading K buffers

    // issue V half0 -> KV0, V half1 -> KV1 (overlap with softmax scalars)
    for (int idx = tid; idx < 2048; idx += 256) {
        int d = idx >> 5, s = idx & 31;
        cp16(&KV0[d * 528 + s * 16], &Vg[d * 1024 + s * 16]);
    }
    CP_COMMIT();
    for (int idx = tid; idx < 2048; idx += 256) {
        int d = idx >> 5, s = idx & 31;
        cp16(&KV1[d * 528 + s * 16], &Vg[d * 1024 + 512 + s * 16]);
    }
    CP_COMMIT();

    // ---- softmax: exp2 numerators in-place + row sums ----
    float s6p = g_sc[6] * 8388608.0f;
    float sum0 = 0.f, sum1 = 0.f;
    #pragma unroll
    for (int j = 0; j < 16; j++) {
        float p0 = pexp2i(acc[j][0], s6p);
        float p1 = pexp2i(acc[j][1], s6p);
        float p2 = pexp2i(acc[j][2], s6p);
        float p3 = pexp2i(acc[j][3], s6p);
        acc[j][0] = __float_as_int(p0); acc[j][1] = __float_as_int(p1);
        acc[j][2] = __float_as_int(p2); acc[j][3] = __float_as_int(p3);
        sum0 += p0 + p1;
        sum1 += p2 + p3;
    }
    sum0 += __shfl_xor_sync(0xffffffffu, sum0, 1);
    sum0 += __shfl_xor_sync(0xffffffffu, sum0, 2);
    sum1 += __shfl_xor_sync(0xffffffffu, sum1, 1);
    sum1 += __shfl_xor_sync(0xffffffffu, sum1, 2);
    if (q4 == 0) {
        atomicAdd(&rs[g], sum0);
        atomicAdd(&rs[g + 8], sum1);
    }
    __syncthreads();
    if (tid < 16) rs[tid] = 1.0f / (rs[tid] * g_sc[4]);
    __syncthreads();

    // ---- quantize attn into Asm ----
    float iv0 = rs[g], iv1 = rs[g + 8];
    #pragma unroll
    for (int j = 0; j < 16; j++) {
        int col = (j >> 3) * 512 + w * 64 + (j & 7) * 8 + q4 * 2;
        uint8_t v0 = (uint8_t)q8p(__int_as_float(acc[j][0]) * iv0);
        uint8_t v1 = (uint8_t)q8p(__int_as_float(acc[j][1]) * iv0);
        *(uint16_t*)&Asm[g * 1040 + col] = (uint16_t)v0 | ((uint16_t)v1 << 8);
        uint8_t v2 = (uint8_t)q8p(__int_as_float(acc[j][2]) * iv1);
        uint8_t v3 = (uint8_t)q8p(__int_as_float(acc[j][3]) * iv1);
        *(uint16_t*)&Asm[(g + 8) * 1040 + col] = (uint16_t)v2 | ((uint16_t)v3 << 8);
    }
    CP_WAIT1();        // V half0 landed
    __syncthreads();   // Asm + V0 visible to all

    // ---- PV half0 (KV0) ----
    int pv[4] = {0, 0, 0, 0};
    #pragma unroll 4
    for (int ksl = 0; ksl < 512; ksl += 32) {
        const int8_t* ap0 = &Asm[g * 1040 + ksl + q4 * 4];
        uint32_t a0 = *(const uint32_t*)ap0;
        uint32_t a2 = *(const uint32_t*)(ap0 + 16);
        const int8_t* ap1 = ap0 + 8 * 1040;
        uint32_t a1 = *(const uint32_t*)ap1;
        uint32_t a3 = *(const uint32_t*)(ap1 + 16);
        const int8_t* bp = &KV0[(w * 8 + g) * 528 + ksl + q4 * 4];
        uint32_t b0 = *(const uint32_t*)bp;
        uint32_t b1 = *(const uint32_t*)(bp + 16);
        MMA_S8(pv, a0, a1, a2, a3, b0, b1);
    }
    CP_WAIT0();        // V half1 landed
    __syncthreads();
    // ---- PV half1 (KV1) ----
    #pragma unroll 4
    for (int ksl = 0; ksl < 512; ksl += 32) {
        const int8_t* ap0 = &Asm[g * 1040 + 512 + ksl + q4 * 4];
        uint32_t a0 = *(const uint32_t*)ap0;
        uint32_t a2 = *(const uint32_t*)(ap0 + 16);
        const int8_t* ap1 = ap0 + 8 * 1040;
        uint32_t a1 = *(const uint32_t*)ap1;
        uint32_t a3 = *(const uint32_t*)(ap1 + 16);
        const int8_t* bp = &KV1[(w * 8 + g) * 528 + ksl + q4 * 4];
        uint32_t b0 = *(const uint32_t*)bp;
        uint32_t b1 = *(const uint32_t*)(bp + 16);
        MMA_S8(pv, a0, a1, a2, a3, b0, b1);
    }

    // ---- epilogue ----
    float r9 = g_sc[9];
    #pragma unroll
    for (int v = 0; v < 4; v++) {
        int rr = qBase + g + (v >> 1) * 8;
        int cc = w * 8 + q4 * 2 + (v & 1);
        g_x1q[((long)(b * SEQ + rr)) * CH + h * HDIM + cc] = q8((float)pv[v] * r9);
    }
}

// ---------------- launcher ----------------
extern "C" void kernel_launch(void* const* d_in, const int* in_sizes, int n_in,
                              void* d_out, int out_size) {
    const float* x0             = (const float*)d_in[0];
    const float* qkv_w          = (const float*)d_in[1];
    const float* qkv_b          = (const float*)d_in[2];
    const float* qkv_alpha      = (const float*)d_in[3];
    const float* qkv_act_alpha  = (const float*)d_in[4];
    const float* proj_w         = (const float*)d_in[5];
    const float* proj_b         = (const float*)d_in[6];
    const float* proj_alpha     = (const float*)d_in[7];
    const float* proj_act_alpha = (const float*)d_in[8];
    const float* norm_q_w       = (const float*)d_in[9];
    const float* norm_q_b       = (const float*)d_in[10];
    const float* norm_k_w       = (const float*)d_in[11];
    const float* norm_k_b       = (const float*)d_in[12];
    const float* q_alpha        = (const float*)d_in[13];
    const float* k_alpha        = (const float*)d_in[14];
    const float* v_alpha        = (const float*)d_in[15];
    const float* attn_alpha     = (const float*)d_in[16];
    float* out = (float*)d_out;

    cudaFuncSetAttribute(k_attn_fused, cudaFuncAttributeMaxDynamicSharedMemorySize, SMEM_ATT);
    cudaFuncSetAttribute(gemm_s8<0>, cudaFuncAttributeMaxDynamicSharedMemorySize, GSM0);
    cudaFuncSetAttribute(gemm_s8<1>, cudaFuncAttributeMaxDynamicSharedMemorySize, GSM1);

    // 1
    k_pre<<<1, 256>>>(qkv_act_alpha, proj_act_alpha, q_alpha, k_alpha, v_alpha,
                      attn_alpha, qkv_alpha, proj_alpha, qkv_b);
    // 2
    k_quant_all<<<(NG_ALL + 255) / 256, 256>>>(x0, qkv_w, proj_w);
    // 3: QKV GEMM + fused norm -> q2/k2/v2t
    gemm_s8<0><<<dim3(C3v / 128, ROWS / 128, 1), 256, GSM0>>>(
        nullptr, qkv_alpha, norm_q_w, norm_q_b, norm_k_w, norm_k_b, nullptr, nullptr);
    // 4 (ncu capture target): fused attention, double-buffered
    k_attn_fused<<<dim3(SEQ / 16, NBH), 256, SMEM_ATT>>>();
    // 5: projection GEMM, 128x64 tiles (384 CTAs -> better wave balance)
    gemm_s8<1><<<dim3(CH / 64, ROWS / 128, 1), 256, GSM1>>>(
        out, qkv_alpha, norm_q_w, norm_q_b, norm_k_w, norm_k_b, proj_alpha, proj_b);
}